// round 7
// baseline (speedup 1.0000x reference)
#include <cuda_runtime.h>
#include <cuda_bf16.h>
#include <cstdint>

#define NTH 512
constexpr int TB   = 128;
constexpr int NH   = 100;
constexpr int NPAD = 112;
constexpr int KD   = 64;
constexpr int DIMS = 8;
constexpr int TOT  = 512;
constexpr int WKS  = 120;   // halves: stride for W2/W3/H buffers (conflict-free ldmatrix)
constexpr int W1KS = 72;    // halves: W1 slice stride
constexpr int ZBS  = 72;    // halves: z-buffer stride (36 words)

// shared layout (word offsets)
constexpr int O_W2S = 0;                    // [112][60w]
constexpr int O_W2T = O_W2S + NPAD * 60;    // 6720
constexpr int O_W3S = O_W2T + NPAD * 60;    // 13440 [64][60w]
constexpr int O_W3T = O_W3S + 64 * 60;      // 17280
constexpr int O_W1S = O_W3T + 64 * 60;      // 21120 [112][36w]
constexpr int O_W1T = O_W1S + NPAD * 36;    // 25152
constexpr int O_HB1 = O_W1T + NPAD * 36;    // 29184 [128][60w]
constexpr int O_HB2 = O_HB1 + TB * 60;      // 36864 [128][60w]
constexpr int O_ZB  = O_HB2 + TB * 60;      // 44544 [128][36w] bf16 z
constexpr int O_LDP = O_ZB + TB * 36;       // 49152 [128][8]
constexpr int O_B1S = O_LDP + TB * 8;       // 50176
constexpr int O_B2S = O_B1S + NPAD;
constexpr int O_B3S = O_B2S + NPAD;
constexpr int O_B1T = O_B3S + KD;
constexpr int O_B2T = O_B1T + NPAD;
constexpr int O_B3T = O_B2T + NPAD;
constexpr int SMW   = O_B3T + KD;           // 50752 words = 203008 B

__device__ __forceinline__ float sigm(float x) {
    return __fdividef(1.0f, 1.0f + __expf(-x));
}

__device__ __forceinline__ uint32_t sm_u32(const void* p) {
    uint32_t a;
    asm("{ .reg .u64 t; cvta.to.shared.u64 t, %1; cvt.u32.u64 %0, t; }" : "=r"(a) : "l"(p));
    return a;
}

// 64-thread named barrier: the two warps sharing an m-tile (same mw, both nw)
__device__ __forceinline__ void bar_pair(int id) {
    asm volatile("bar.sync %0, 64;" :: "r"(id) : "memory");
}

__device__ __forceinline__ void ldsm4(uint32_t a, uint32_t r[4]) {
    asm volatile("ldmatrix.sync.aligned.m8n8.x4.shared.b16 {%0,%1,%2,%3},[%4];"
                 : "=r"(r[0]), "=r"(r[1]), "=r"(r[2]), "=r"(r[3]) : "r"(a));
}
__device__ __forceinline__ void ldsm2(uint32_t a, uint32_t r[2]) {
    asm volatile("ldmatrix.sync.aligned.m8n8.x2.shared.b16 {%0,%1},[%2];"
                 : "=r"(r[0]), "=r"(r[1]) : "r"(a));
}

__device__ __forceinline__ void mma_bf(float* c, const uint32_t* a, uint32_t b0, uint32_t b1) {
    asm volatile(
        "mma.sync.aligned.m16n8k16.row.col.f32.bf16.bf16.f32 "
        "{%0,%1,%2,%3},{%4,%5,%6,%7},{%8,%9},{%0,%1,%2,%3};"
        : "+f"(c[0]), "+f"(c[1]), "+f"(c[2]), "+f"(c[3])
        : "r"(a[0]), "r"(a[1]), "r"(a[2]), "r"(a[3]), "r"(b0), "r"(b1));
}

// C[NT n8] (+)= A[m16 x 16*KSTEPS] @ B; one m-tile per warp.
template <int KSTEPS, int NT, int BKS>
__device__ __forceinline__ void gemm1m(uint32_t aA, uint32_t bA, uint32_t bAo,
                                       float c[NT][4]) {
#pragma unroll
    for (int ks = 0; ks < KSTEPS; ks++) {
        uint32_t a[4];
        ldsm4(aA, a);
#pragma unroll
        for (int p = 0; p < NT / 2; p++) {
            uint32_t b[4];
            ldsm4(bA + p * (16 * BKS * 2), b);
            mma_bf(c[2 * p],     a, b[0], b[1]);
            mma_bf(c[2 * p + 1], a, b[2], b[3]);
        }
        if constexpr (NT & 1) {
            uint32_t b[2];
            ldsm2(bAo, b);
            mma_bf(c[NT - 1], a, b[0], b[1]);
        }
        aA += 32; bA += 32; bAo += 32;
    }
}

// relu(c + bias) -> bf16x2 -> hb (word stride 60)
template <int NT>
__device__ __forceinline__ void store_h(const float c[NT][4], const float* __restrict__ bias,
                                        uint32_t* __restrict__ hb, int nb, int mrow, int g, int t) {
#pragma unroll
    for (int nt = 0; nt < NT; nt++) {
        int cc = nb + nt * 8 + 2 * t;
        float2 b = *(const float2*)&bias[cc];
#pragma unroll
        for (int h = 0; h < 2; h++) {
            int row = mrow + h * 8 + g;
            float v0 = fmaxf(c[nt][2 * h + 0] + b.x, 0.f);
            float v1 = fmaxf(c[nt][2 * h + 1] + b.y, 0.f);
            __nv_bfloat162 p = __floats2bfloat162_rn(v0, v1);
            hb[row * 60 + (cc >> 1)] = *(uint32_t*)&p;
        }
    }
}

// stage W1 slice [64 k][100 n] fp32 -> [112 n][72 k-stride] bf16 (pad pre-zeroed)
__device__ __forceinline__ void stageW1(const float* __restrict__ Wg,
                                        __nv_bfloat16* __restrict__ dst, int tid) {
#pragma unroll 1
    for (int idx = tid; idx < KD * NH; idx += NTH) {
        int kk = idx / NH, n = idx - kk * NH;
        dst[n * W1KS + kk] = __float2bfloat16(Wg[idx]);
    }
}

__global__ void __launch_bounds__(NTH, 1) flow_bf16(
    const float* __restrict__ e,
    const float* __restrict__ sW1, const float* __restrict__ sb1,
    const float* __restrict__ sW2, const float* __restrict__ sb2,
    const float* __restrict__ sW3, const float* __restrict__ sb3,
    const float* __restrict__ tW1, const float* __restrict__ tb1,
    const float* __restrict__ tW2, const float* __restrict__ tb2,
    const float* __restrict__ tW3, const float* __restrict__ tb3,
    float* __restrict__ zout, float* __restrict__ ldout)
{
    extern __shared__ float smf[];
    uint32_t* smu = (uint32_t*)smf;
    __nv_bfloat16* smh = (__nv_bfloat16*)smf;

    const int tid = threadIdx.x;
    const int lane = tid & 31, wid = tid >> 5;
    const int g = lane >> 2, t = lane & 3;
    const int mw = wid & 7, nw = wid >> 3;   // 8 m-warps x 2 n-groups
    const int mrow = mw * 16;
    const int nb2 = nw * 56;   // GEMM1/2: 7 n-tiles per group
    const int nb3 = nw * 32;   // GEMM3:   4 n-tiles per group
    const int pairBar = 1 + mw;              // named barrier id for this m-pair
    const long rowBase = (long)blockIdx.x * TB;

    // ---- preload: zero weight regions, fill transposed bf16 weights + biases ----
    for (int w = tid; w < O_HB1; w += NTH) smu[w] = 0u;
    __syncthreads();
    for (int idx = tid; idx < NH * NH; idx += NTH) {
        int in = idx / NH, out = idx - in * NH;
        smh[O_W2S * 2 + out * WKS + in] = __float2bfloat16(sW2[idx]);
        smh[O_W2T * 2 + out * WKS + in] = __float2bfloat16(tW2[idx]);
    }
    for (int idx = tid; idx < NH * KD; idx += NTH) {
        int in = idx / KD, out = idx - in * KD;
        smh[O_W3S * 2 + out * WKS + in] = __float2bfloat16(sW3[idx]);
        smh[O_W3T * 2 + out * WKS + in] = __float2bfloat16(tW3[idx]);
    }
    for (int idx = tid; idx < NPAD; idx += NTH) {
        smf[O_B1S + idx] = (idx < NH) ? sb1[idx] : 0.f;
        smf[O_B2S + idx] = (idx < NH) ? sb2[idx] : 0.f;
        smf[O_B1T + idx] = (idx < NH) ? tb1[idx] : 0.f;
        smf[O_B2T + idx] = (idx < NH) ? tb2[idx] : 0.f;
    }
    for (int idx = tid; idx < KD; idx += NTH) {
        smf[O_B3S + idx] = sb3[idx];
        smf[O_B3T + idx] = tb3[idx];
    }

    // ---- ldmatrix address precompute ----
    const uint32_t smb = sm_u32(smf);
    const int aRow = lane & 15, aK = (lane >> 4) << 3;
    const uint32_t aHB1 = smb + O_HB1 * 4 + ((mrow + aRow) * WKS + aK) * 2;
    const uint32_t aHB2 = smb + O_HB2 * 4 + ((mrow + aRow) * WKS + aK) * 2;
    const uint32_t aZB  = smb + O_ZB  * 4 + ((mrow + aRow) * ZBS + aK) * 2;
    const int bRow  = (lane & 7) + ((lane >> 4) << 3);
    const int bK    = ((lane >> 3) & 1) << 3;
    const int bORow = lane & 7;
    const uint32_t bW2S  = smb + O_W2S * 4 + ((nb2 + bRow) * WKS + bK) * 2;
    const uint32_t bW2So = smb + O_W2S * 4 + ((nb2 + 48 + bORow) * WKS + bK) * 2;
    const uint32_t bW2T  = smb + O_W2T * 4 + ((nb2 + bRow) * WKS + bK) * 2;
    const uint32_t bW2To = smb + O_W2T * 4 + ((nb2 + 48 + bORow) * WKS + bK) * 2;
    const uint32_t bW3S  = smb + O_W3S * 4 + ((nb3 + bRow) * WKS + bK) * 2;
    const uint32_t bW3T  = smb + O_W3T * 4 + ((nb3 + bRow) * WKS + bK) * 2;
    const uint32_t bW1S  = smb + O_W1S * 4 + ((nb2 + bRow) * W1KS + bK) * 2;
    const uint32_t bW1So = smb + O_W1S * 4 + ((nb2 + 48 + bORow) * W1KS + bK) * 2;
    const uint32_t bW1T  = smb + O_W1T * 4 + ((nb2 + bRow) * W1KS + bK) * 2;
    const uint32_t bW1To = smb + O_W1T * 4 + ((nb2 + 48 + bORow) * W1KS + bK) * 2;

    // persistent layer-1 accumulators: 1 m-tile x 7 n-tiles each
    float accS[7][4], accT[7][4];
#pragma unroll
    for (int b = 0; b < 7; b++)
#pragma unroll
        for (int q = 0; q < 4; q++) { accS[b][q] = 0.f; accT[b][q] = 0.f; }
    float ldacc[2] = {0.f, 0.f};

    __syncthreads();

    // Barrier schedule (per step):
    //   A-end: pair   (HB1 h1s writes/reads are m-pair row-local)
    //   B-end: FULL   (orders all pairs' phase-A W1 reads before phase-C W1S restage)
    //   C-end: pair   (HB1 h1t, row-local; W1S stage writes tid-disjoint, consumed next step)
    //   D-end: pair   (HB2 h2t, row-local)
    //   E-end: FULL   (orders W1S/W1T staging + ZB before next step's phase A)
    for (int i = 0; i < DIMS; i++) {
        // ---- A: acc += z_{i-1} @ W1[i-1]; h1s -> HB1 ----
        if (i > 0) {
            gemm1m<4, 7, W1KS>(aZB, bW1S, bW1So, accS);
            gemm1m<4, 7, W1KS>(aZB, bW1T, bW1To, accT);
        }
        store_h<7>(accS, smf + O_B1S, smu + O_HB1, nb2, mrow, g, t);
        bar_pair(pairBar);

        // ---- B: GEMM2-s ----
        {
            float D[7][4] = {};
            gemm1m<7, 7, WKS>(aHB1, bW2S, bW2So, D);
            store_h<7>(D, smf + O_B2S, smu + O_HB2, nb2, mrow, g, t);
        }
        __syncthreads();

        // ---- C: GEMM3-s -> sv (regs) + logdet; h1t -> HB1; stage W1s slice i ----
        float sv[4][4];
        {
            float Ds[4][4] = {};
            gemm1m<7, 4, WKS>(aHB2, bW3S, 0, Ds);
#pragma unroll
            for (int nt = 0; nt < 4; nt++) {
                int cc = nb3 + nt * 8 + 2 * t;
                float2 b3 = *(const float2*)&smf[O_B3S + cc];
#pragma unroll
                for (int h = 0; h < 2; h++) {
                    float v0 = sigm(Ds[nt][2 * h + 0] + b3.x);
                    float v1 = sigm(Ds[nt][2 * h + 1] + b3.y);
                    sv[nt][2 * h + 0] = v0;
                    sv[nt][2 * h + 1] = v1;
                    ldacc[h] += v0 + v1;
                }
            }
            store_h<7>(accT, smf + O_B1T, smu + O_HB1, nb2, mrow, g, t);
            if (i < DIMS - 1) stageW1(sW1 + (size_t)i * KD * NH, smh + O_W1S * 2, tid);
        }
        bar_pair(pairBar);

        // ---- D: GEMM2-t; stage W1t slice i ----
        {
            float D[7][4] = {};
            gemm1m<7, 7, WKS>(aHB1, bW2T, bW2To, D);
            store_h<7>(D, smf + O_B2T, smu + O_HB2, nb2, mrow, g, t);
            if (i < DIMS - 1) stageW1(tW1 + (size_t)i * KD * NH, smh + O_W1T * 2, tid);
        }
        bar_pair(pairBar);

        // ---- E: prefetch e; GEMM3-t -> t; z = exp(sv)*e + t; STG + z(bf16) -> ZB ----
        {
            float2 eV[8];
#pragma unroll
            for (int nt = 0; nt < 4; nt++)
#pragma unroll
                for (int h = 0; h < 2; h++) {
                    int row = mrow + h * 8 + g;
                    eV[nt * 2 + h] = *(const float2*)&e[(rowBase + row) * TOT + i * KD + nb3 + nt * 8 + 2 * t];
                }

            float Dt[4][4] = {};
            gemm1m<7, 4, WKS>(aHB2, bW3T, 0, Dt);
#pragma unroll
            for (int nt = 0; nt < 4; nt++) {
                int cc = nb3 + nt * 8 + 2 * t;
                float2 b3 = *(const float2*)&smf[O_B3T + cc];
#pragma unroll
                for (int h = 0; h < 2; h++) {
                    int row = mrow + h * 8 + g;
                    long gidx = (rowBase + row) * TOT + i * KD + cc;
                    float t0 = sigm(Dt[nt][2 * h + 0] + b3.x);
                    float t1 = sigm(Dt[nt][2 * h + 1] + b3.y);
                    float2 e2 = eV[nt * 2 + h];
                    float z0 = __expf(sv[nt][2 * h + 0]) * e2.x + t0;
                    float z1 = __expf(sv[nt][2 * h + 1]) * e2.y + t1;
                    *(float2*)&zout[gidx] = make_float2(z0, z1);
                    __nv_bfloat162 zb = __floats2bfloat162_rn(z0, z1);
                    smu[O_ZB + row * 36 + (cc >> 1)] = *(uint32_t*)&zb;
                }
            }
        }
        __syncthreads();
    }

    // ---- logdet reduction: 8 partials per row ----
#pragma unroll
    for (int h = 0; h < 2; h++) {
        int row = mrow + h * 8 + g;
        smf[O_LDP + row * 8 + nw * 4 + t] = ldacc[h];
    }
    __syncthreads();
    if (tid < TB) {
        float v = 0.f;
#pragma unroll
        for (int q = 0; q < 8; q++) v += smf[O_LDP + tid * 8 + q];
        ldout[rowBase + tid] = v;
    }
}

extern "C" void kernel_launch(void* const* d_in, const int* in_sizes, int n_in,
                              void* d_out, int out_size) {
    const float* e   = (const float*)d_in[0];
    // d_in[1] = C (strictly upper-triangular DAG -> incremental layer-1 acc is exact)
    const float* sW1 = (const float*)d_in[2];
    const float* sb1 = (const float*)d_in[3];
    const float* sW2 = (const float*)d_in[4];
    const float* sb2 = (const float*)d_in[5];
    const float* sW3 = (const float*)d_in[6];
    const float* sb3 = (const float*)d_in[7];
    const float* tW1 = (const float*)d_in[8];
    const float* tb1 = (const float*)d_in[9];
    const float* tW2 = (const float*)d_in[10];
    const float* tb2 = (const float*)d_in[11];
    const float* tW3 = (const float*)d_in[12];
    const float* tb3 = (const float*)d_in[13];

    float* out = (float*)d_out;
    const int B = in_sizes[0] / TOT;
    float* zout  = out;
    float* ldout = out + (size_t)B * TOT;

    cudaFuncSetAttribute(flow_bf16, cudaFuncAttributeMaxDynamicSharedMemorySize,
                         SMW * (int)sizeof(float));

    flow_bf16<<<B / TB, NTH, SMW * sizeof(float)>>>(
        e, sW1, sb1, sW2, sb2, sW3, sb3,
        tW1, tb1, tW2, tb2, tW3, tb3,
        zout, ldout);
}

// round 8
// speedup vs baseline: 1.1070x; 1.1070x over previous
#include <cuda_runtime.h>
#include <cuda_bf16.h>
#include <cstdint>

#define NTH 512
constexpr int TB   = 128;
constexpr int NH   = 100;
constexpr int NPAD = 112;
constexpr int KD   = 64;
constexpr int DIMS = 8;
constexpr int TOT  = 512;
constexpr int WKS  = 120;   // halves: stride for W2/W3/H buffers (conflict-free ldmatrix)
constexpr int W1KS = 72;    // halves: W1 slice stride
constexpr int ZBS  = 72;    // halves: z-buffer stride (36 words)
constexpr int W1N  = 13;    // ceil(KD*NH / NTH) registers for W1 prefetch

// shared layout (word offsets)
constexpr int O_W2S = 0;                    // [112][60w]
constexpr int O_W2T = O_W2S + NPAD * 60;    // 6720
constexpr int O_W3S = O_W2T + NPAD * 60;    // 13440 [64][60w]
constexpr int O_W3T = O_W3S + 64 * 60;      // 17280
constexpr int O_W1S = O_W3T + 64 * 60;      // 21120 [112][36w]
constexpr int O_W1T = O_W1S + NPAD * 36;    // 25152
constexpr int O_HB1 = O_W1T + NPAD * 36;    // 29184 [128][60w]
constexpr int O_HB2 = O_HB1 + TB * 60;      // 36864 [128][60w]
constexpr int O_ZB  = O_HB2 + TB * 60;      // 44544 [128][36w] bf16 z
constexpr int O_LDP = O_ZB + TB * 36;       // 49152 [128][8]
constexpr int O_B1S = O_LDP + TB * 8;       // 50176
constexpr int O_B2S = O_B1S + NPAD;
constexpr int O_B3S = O_B2S + NPAD;
constexpr int O_B1T = O_B3S + KD;
constexpr int O_B2T = O_B1T + NPAD;
constexpr int O_B3T = O_B2T + NPAD;
constexpr int SMW   = O_B3T + KD;           // 50752 words = 203008 B

__device__ __forceinline__ float sigm(float x) {
    return __fdividef(1.0f, 1.0f + __expf(-x));
}

__device__ __forceinline__ uint32_t sm_u32(const void* p) {
    uint32_t a;
    asm("{ .reg .u64 t; cvta.to.shared.u64 t, %1; cvt.u32.u64 %0, t; }" : "=r"(a) : "l"(p));
    return a;
}

__device__ __forceinline__ void ldsm4(uint32_t a, uint32_t r[4]) {
    asm volatile("ldmatrix.sync.aligned.m8n8.x4.shared.b16 {%0,%1,%2,%3},[%4];"
                 : "=r"(r[0]), "=r"(r[1]), "=r"(r[2]), "=r"(r[3]) : "r"(a));
}
__device__ __forceinline__ void ldsm2(uint32_t a, uint32_t r[2]) {
    asm volatile("ldmatrix.sync.aligned.m8n8.x2.shared.b16 {%0,%1},[%2];"
                 : "=r"(r[0]), "=r"(r[1]) : "r"(a));
}

__device__ __forceinline__ void mma_bf(float* c, const uint32_t* a, uint32_t b0, uint32_t b1) {
    asm volatile(
        "mma.sync.aligned.m16n8k16.row.col.f32.bf16.bf16.f32 "
        "{%0,%1,%2,%3},{%4,%5,%6,%7},{%8,%9},{%0,%1,%2,%3};"
        : "+f"(c[0]), "+f"(c[1]), "+f"(c[2]), "+f"(c[3])
        : "r"(a[0]), "r"(a[1]), "r"(a[2]), "r"(a[3]), "r"(b0), "r"(b1));
}

// C[NT n8] (+)= A[m16 x 16*KSTEPS] @ B; one m-tile per warp.
template <int KSTEPS, int NT, int BKS>
__device__ __forceinline__ void gemm1m(uint32_t aA, uint32_t bA, uint32_t bAo,
                                       float c[NT][4]) {
#pragma unroll
    for (int ks = 0; ks < KSTEPS; ks++) {
        uint32_t a[4];
        ldsm4(aA, a);
#pragma unroll
        for (int p = 0; p < NT / 2; p++) {
            uint32_t b[4];
            ldsm4(bA + p * (16 * BKS * 2), b);
            mma_bf(c[2 * p],     a, b[0], b[1]);
            mma_bf(c[2 * p + 1], a, b[2], b[3]);
        }
        if constexpr (NT & 1) {
            uint32_t b[2];
            ldsm2(bAo, b);
            mma_bf(c[NT - 1], a, b[0], b[1]);
        }
        aA += 32; bA += 32; bAo += 32;
    }
}

// relu(c + bias) -> bf16x2 -> hb (word stride 60)
template <int NT>
__device__ __forceinline__ void store_h(const float c[NT][4], const float* __restrict__ bias,
                                        uint32_t* __restrict__ hb, int nb, int mrow, int g, int t) {
#pragma unroll
    for (int nt = 0; nt < NT; nt++) {
        int cc = nb + nt * 8 + 2 * t;
        float2 b = *(const float2*)&bias[cc];
#pragma unroll
        for (int h = 0; h < 2; h++) {
            int row = mrow + h * 8 + g;
            float v0 = fmaxf(c[nt][2 * h + 0] + b.x, 0.f);
            float v1 = fmaxf(c[nt][2 * h + 1] + b.y, 0.f);
            __nv_bfloat162 p = __floats2bfloat162_rn(v0, v1);
            hb[row * 60 + (cc >> 1)] = *(uint32_t*)&p;
        }
    }
}

// W1 staging split: issue LDGs early (latency hides under the phase's GEMM)...
__device__ __forceinline__ void loadW1(const float* __restrict__ Wg, float v[W1N], int tid) {
#pragma unroll
    for (int j = 0; j < W1N; j++) {
        int idx = tid + j * NTH;
        v[j] = (idx < KD * NH) ? Wg[idx] : 0.f;
    }
}
// ...then convert+scatter to [112 n][72 k-stride] bf16 after the GEMM (pad pre-zeroed)
__device__ __forceinline__ void scatW1(const float v[W1N], __nv_bfloat16* __restrict__ dst, int tid) {
#pragma unroll
    for (int j = 0; j < W1N; j++) {
        int idx = tid + j * NTH;
        if (idx < KD * NH) {
            int kk = idx / NH, n = idx - kk * NH;
            dst[n * W1KS + kk] = __float2bfloat16(v[j]);
        }
    }
}

__global__ void __launch_bounds__(NTH, 1) flow_bf16(
    const float* __restrict__ e,
    const float* __restrict__ sW1, const float* __restrict__ sb1,
    const float* __restrict__ sW2, const float* __restrict__ sb2,
    const float* __restrict__ sW3, const float* __restrict__ sb3,
    const float* __restrict__ tW1, const float* __restrict__ tb1,
    const float* __restrict__ tW2, const float* __restrict__ tb2,
    const float* __restrict__ tW3, const float* __restrict__ tb3,
    float* __restrict__ zout, float* __restrict__ ldout)
{
    extern __shared__ float smf[];
    uint32_t* smu = (uint32_t*)smf;
    __nv_bfloat16* smh = (__nv_bfloat16*)smf;

    const int tid = threadIdx.x;
    const int lane = tid & 31, wid = tid >> 5;
    const int g = lane >> 2, t = lane & 3;
    const int mw = wid & 7, nw = wid >> 3;   // 8 m-warps x 2 n-groups
    const int mrow = mw * 16;
    const int nb2 = nw * 56;   // GEMM1/2: 7 n-tiles per group
    const int nb3 = nw * 32;   // GEMM3:   4 n-tiles per group
    const long rowBase = (long)blockIdx.x * TB;

    // ---- preload: zero weight regions, fill transposed bf16 weights + biases ----
    for (int w = tid; w < O_HB1; w += NTH) smu[w] = 0u;
    __syncthreads();
    for (int idx = tid; idx < NH * NH; idx += NTH) {
        int in = idx / NH, out = idx - in * NH;
        smh[O_W2S * 2 + out * WKS + in] = __float2bfloat16(sW2[idx]);
        smh[O_W2T * 2 + out * WKS + in] = __float2bfloat16(tW2[idx]);
    }
    for (int idx = tid; idx < NH * KD; idx += NTH) {
        int in = idx / KD, out = idx - in * KD;
        smh[O_W3S * 2 + out * WKS + in] = __float2bfloat16(sW3[idx]);
        smh[O_W3T * 2 + out * WKS + in] = __float2bfloat16(tW3[idx]);
    }
    for (int idx = tid; idx < NPAD; idx += NTH) {
        smf[O_B1S + idx] = (idx < NH) ? sb1[idx] : 0.f;
        smf[O_B2S + idx] = (idx < NH) ? sb2[idx] : 0.f;
        smf[O_B1T + idx] = (idx < NH) ? tb1[idx] : 0.f;
        smf[O_B2T + idx] = (idx < NH) ? tb2[idx] : 0.f;
    }
    for (int idx = tid; idx < KD; idx += NTH) {
        smf[O_B3S + idx] = sb3[idx];
        smf[O_B3T + idx] = tb3[idx];
    }

    // ---- ldmatrix address precompute ----
    const uint32_t smb = sm_u32(smf);
    const int aRow = lane & 15, aK = (lane >> 4) << 3;
    const uint32_t aHB1 = smb + O_HB1 * 4 + ((mrow + aRow) * WKS + aK) * 2;
    const uint32_t aHB2 = smb + O_HB2 * 4 + ((mrow + aRow) * WKS + aK) * 2;
    const uint32_t aZB  = smb + O_ZB  * 4 + ((mrow + aRow) * ZBS + aK) * 2;
    const int bRow  = (lane & 7) + ((lane >> 4) << 3);
    const int bK    = ((lane >> 3) & 1) << 3;
    const int bORow = lane & 7;
    const uint32_t bW2S  = smb + O_W2S * 4 + ((nb2 + bRow) * WKS + bK) * 2;
    const uint32_t bW2So = smb + O_W2S * 4 + ((nb2 + 48 + bORow) * WKS + bK) * 2;
    const uint32_t bW2T  = smb + O_W2T * 4 + ((nb2 + bRow) * WKS + bK) * 2;
    const uint32_t bW2To = smb + O_W2T * 4 + ((nb2 + 48 + bORow) * WKS + bK) * 2;
    const uint32_t bW3S  = smb + O_W3S * 4 + ((nb3 + bRow) * WKS + bK) * 2;
    const uint32_t bW3T  = smb + O_W3T * 4 + ((nb3 + bRow) * WKS + bK) * 2;
    const uint32_t bW1S  = smb + O_W1S * 4 + ((nb2 + bRow) * W1KS + bK) * 2;
    const uint32_t bW1So = smb + O_W1S * 4 + ((nb2 + 48 + bORow) * W1KS + bK) * 2;
    const uint32_t bW1T  = smb + O_W1T * 4 + ((nb2 + bRow) * W1KS + bK) * 2;
    const uint32_t bW1To = smb + O_W1T * 4 + ((nb2 + 48 + bORow) * W1KS + bK) * 2;

    // persistent layer-1 accumulators: 1 m-tile x 7 n-tiles each
    float accS[7][4], accT[7][4];
#pragma unroll
    for (int b = 0; b < 7; b++)
#pragma unroll
        for (int q = 0; q < 4; q++) { accS[b][q] = 0.f; accT[b][q] = 0.f; }
    float ldacc[2] = {0.f, 0.f};

    __syncthreads();

    for (int i = 0; i < DIMS; i++) {
        // ---- A: acc += z_{i-1} @ W1[i-1]; h1s -> HB1 ----
        if (i > 0) {
            gemm1m<4, 7, W1KS>(aZB, bW1S, bW1So, accS);
            gemm1m<4, 7, W1KS>(aZB, bW1T, bW1To, accT);
        }
        store_h<7>(accS, smf + O_B1S, smu + O_HB1, nb2, mrow, g, t);
        __syncthreads();

        // ---- B: GEMM2-s ----
        {
            float D[7][4] = {};
            gemm1m<7, 7, WKS>(aHB1, bW2S, bW2So, D);
            store_h<7>(D, smf + O_B2S, smu + O_HB2, nb2, mrow, g, t);
        }
        __syncthreads();

        // ---- C: W1s LDGs early; GEMM3-s -> sv (regs) + logdet; h1t -> HB1; scatter W1s ----
        float sv[4][4];
        {
            float w1v[W1N];
            if (i < DIMS - 1) loadW1(sW1 + (size_t)i * KD * NH, w1v, tid);

            float Ds[4][4] = {};
            gemm1m<7, 4, WKS>(aHB2, bW3S, 0, Ds);
#pragma unroll
            for (int nt = 0; nt < 4; nt++) {
                int cc = nb3 + nt * 8 + 2 * t;
                float2 b3 = *(const float2*)&smf[O_B3S + cc];
#pragma unroll
                for (int h = 0; h < 2; h++) {
                    float v0 = sigm(Ds[nt][2 * h + 0] + b3.x);
                    float v1 = sigm(Ds[nt][2 * h + 1] + b3.y);
                    sv[nt][2 * h + 0] = v0;
                    sv[nt][2 * h + 1] = v1;
                    ldacc[h] += v0 + v1;
                }
            }
            store_h<7>(accT, smf + O_B1T, smu + O_HB1, nb2, mrow, g, t);
            if (i < DIMS - 1) scatW1(w1v, smh + O_W1S * 2, tid);
        }
        __syncthreads();

        // ---- D: W1t LDGs early; GEMM2-t; scatter W1t ----
        {
            float w1v[W1N];
            if (i < DIMS - 1) loadW1(tW1 + (size_t)i * KD * NH, w1v, tid);

            float D[7][4] = {};
            gemm1m<7, 7, WKS>(aHB1, bW2T, bW2To, D);
            store_h<7>(D, smf + O_B2T, smu + O_HB2, nb2, mrow, g, t);
            if (i < DIMS - 1) scatW1(w1v, smh + O_W1T * 2, tid);
        }
        __syncthreads();

        // ---- E: prefetch e; GEMM3-t -> t; z = exp(sv)*e + t; STG + z(bf16) -> ZB ----
        {
            float2 eV[8];
#pragma unroll
            for (int nt = 0; nt < 4; nt++)
#pragma unroll
                for (int h = 0; h < 2; h++) {
                    int row = mrow + h * 8 + g;
                    eV[nt * 2 + h] = *(const float2*)&e[(rowBase + row) * TOT + i * KD + nb3 + nt * 8 + 2 * t];
                }

            float Dt[4][4] = {};
            gemm1m<7, 4, WKS>(aHB2, bW3T, 0, Dt);
#pragma unroll
            for (int nt = 0; nt < 4; nt++) {
                int cc = nb3 + nt * 8 + 2 * t;
                float2 b3 = *(const float2*)&smf[O_B3T + cc];
#pragma unroll
                for (int h = 0; h < 2; h++) {
                    int row = mrow + h * 8 + g;
                    long gidx = (rowBase + row) * TOT + i * KD + cc;
                    float t0 = sigm(Dt[nt][2 * h + 0] + b3.x);
                    float t1 = sigm(Dt[nt][2 * h + 1] + b3.y);
                    float2 e2 = eV[nt * 2 + h];
                    float z0 = __expf(sv[nt][2 * h + 0]) * e2.x + t0;
                    float z1 = __expf(sv[nt][2 * h + 1]) * e2.y + t1;
                    *(float2*)&zout[gidx] = make_float2(z0, z1);
                    __nv_bfloat162 zb = __floats2bfloat162_rn(z0, z1);
                    smu[O_ZB + row * 36 + (cc >> 1)] = *(uint32_t*)&zb;
                }
            }
        }
        __syncthreads();
    }

    // ---- logdet reduction: 8 partials per row ----
#pragma unroll
    for (int h = 0; h < 2; h++) {
        int row = mrow + h * 8 + g;
        smf[O_LDP + row * 8 + nw * 4 + t] = ldacc[h];
    }
    __syncthreads();
    if (tid < TB) {
        float v = 0.f;
#pragma unroll
        for (int q = 0; q < 8; q++) v += smf[O_LDP + tid * 8 + q];
        ldout[rowBase + tid] = v;
    }
}

extern "C" void kernel_launch(void* const* d_in, const int* in_sizes, int n_in,
                              void* d_out, int out_size) {
    const float* e   = (const float*)d_in[0];
    // d_in[1] = C (strictly upper-triangular DAG -> incremental layer-1 acc is exact)
    const float* sW1 = (const float*)d_in[2];
    const float* sb1 = (const float*)d_in[3];
    const float* sW2 = (const float*)d_in[4];
    const float* sb2 = (const float*)d_in[5];
    const float* sW3 = (const float*)d_in[6];
    const float* sb3 = (const float*)d_in[7];
    const float* tW1 = (const float*)d_in[8];
    const float* tb1 = (const float*)d_in[9];
    const float* tW2 = (const float*)d_in[10];
    const float* tb2 = (const float*)d_in[11];
    const float* tW3 = (const float*)d_in[12];
    const float* tb3 = (const float*)d_in[13];

    float* out = (float*)d_out;
    const int B = in_sizes[0] / TOT;
    float* zout  = out;
    float* ldout = out + (size_t)B * TOT;

    cudaFuncSetAttribute(flow_bf16, cudaFuncAttributeMaxDynamicSharedMemorySize,
                         SMW * (int)sizeof(float));

    flow_bf16<<<B / TB, NTH, SMW * sizeof(float)>>>(
        e, sW1, sb1, sW2, sb2, sW3, sb3,
        tW1, tb1, tW2, tb2, tW3, tb3,
        zout, ldout);
}

// round 9
// speedup vs baseline: 1.2080x; 1.0913x over previous
#include <cuda_runtime.h>
#include <cuda_bf16.h>
#include <cstdint>

#define NTH 512
constexpr int TB    = 128;
constexpr int NH    = 100;
constexpr int NPADK = 112;  // k-dim padding (7 k16-steps)
constexpr int NPADN = 104;  // n-dim rows for W2/W1 buffers (13 n8-tiles, 7/6 split)
constexpr int KD    = 64;
constexpr int DIMS  = 8;
constexpr int TOT   = 512;
constexpr int WKS   = 120;  // halves: k-stride for W2/W3/H buffers (conflict-free ldmatrix)
constexpr int W1KS  = 72;   // halves: W1 slice k-stride
constexpr int ZBS   = 72;   // halves: z-buffer stride
constexpr int W1N   = 13;   // ceil(KD*NH / NTH) regs for W1 prefetch
constexpr int W1PARB = 3744 * 4;  // parity offset, bytes
constexpr int W1PARH = 3744 * 2;  // parity offset, halves

// shared layout (word offsets)
constexpr int O_W2S  = 0;                      // [104][60w]
constexpr int O_W2T  = O_W2S + NPADN * 60;     // 6240
constexpr int O_W3S  = O_W2T + NPADN * 60;     // 12480 [64][60w]
constexpr int O_W3T  = O_W3S + 64 * 60;        // 16320
constexpr int O_W1S0 = O_W3T + 64 * 60;        // 20160 [104][36w] x2 parity
constexpr int O_W1T0 = O_W1S0 + 2 * NPADN * 36;// 27648 [104][36w] x2 parity
constexpr int O_HB1  = O_W1T0 + 2 * NPADN * 36;// 35136 [128][60w]
constexpr int O_HB2  = O_HB1 + TB * 60;        // 42816 [128][60w]
constexpr int O_ZB   = O_HB2 + TB * 60;        // 50496 [128][36w] bf16 z (post-loop: logdet scratch)
constexpr int O_LDP  = O_ZB;                   // alias (ZB dead after last step's phase A)
constexpr int O_B1S  = O_ZB + TB * 36;         // 55104
constexpr int O_B2S  = O_B1S + NPADK;
constexpr int O_B3S  = O_B2S + NPADK;
constexpr int O_B1T  = O_B3S + KD;
constexpr int O_B2T  = O_B1T + NPADK;
constexpr int O_B3T  = O_B2T + NPADK;
constexpr int SMW    = O_B3T + KD;             // 55680 words = 222720 B

__device__ __forceinline__ float sigm(float x) {
    return __fdividef(1.0f, 1.0f + __expf(-x));
}

__device__ __forceinline__ uint32_t sm_u32(const void* p) {
    uint32_t a;
    asm("{ .reg .u64 t; cvta.to.shared.u64 t, %1; cvt.u32.u64 %0, t; }" : "=r"(a) : "l"(p));
    return a;
}

// 64-thread named barrier for the two warps sharing an m-tile
__device__ __forceinline__ void bar_pair(int id) {
    asm volatile("bar.sync %0, 64;" :: "r"(id) : "memory");
}

__device__ __forceinline__ void ldsm4(uint32_t a, uint32_t r[4]) {
    asm volatile("ldmatrix.sync.aligned.m8n8.x4.shared.b16 {%0,%1,%2,%3},[%4];"
                 : "=r"(r[0]), "=r"(r[1]), "=r"(r[2]), "=r"(r[3]) : "r"(a));
}
__device__ __forceinline__ void ldsm2(uint32_t a, uint32_t r[2]) {
    asm volatile("ldmatrix.sync.aligned.m8n8.x2.shared.b16 {%0,%1},[%2];"
                 : "=r"(r[0]), "=r"(r[1]) : "r"(a));
}

__device__ __forceinline__ void mma_bf(float* c, const uint32_t* a, uint32_t b0, uint32_t b1) {
    asm volatile(
        "mma.sync.aligned.m16n8k16.row.col.f32.bf16.bf16.f32 "
        "{%0,%1,%2,%3},{%4,%5,%6,%7},{%8,%9},{%0,%1,%2,%3};"
        : "+f"(c[0]), "+f"(c[1]), "+f"(c[2]), "+f"(c[3])
        : "r"(a[0]), "r"(a[1]), "r"(a[2]), "r"(a[3]), "r"(b0), "r"(b1));
}

// C[NT n8] (+)= A[m16 x 16*KSTEPS] @ B; one m-tile per warp.
template <int KSTEPS, int NT, int BKS>
__device__ __forceinline__ void gemm1m(uint32_t aA, uint32_t bA, uint32_t bAo,
                                       float c[][4]) {
#pragma unroll
    for (int ks = 0; ks < KSTEPS; ks++) {
        uint32_t a[4];
        ldsm4(aA, a);
#pragma unroll
        for (int p = 0; p < NT / 2; p++) {
            uint32_t b[4];
            ldsm4(bA + p * (16 * BKS * 2), b);
            mma_bf(c[2 * p],     a, b[0], b[1]);
            mma_bf(c[2 * p + 1], a, b[2], b[3]);
        }
        if constexpr (NT & 1) {
            uint32_t b[2];
            ldsm2(bAo, b);
            mma_bf(c[NT - 1], a, b[0], b[1]);
        }
        aA += 32; bA += 32; bAo += 32;
    }
}

// Dual-B gemm sharing A-fragments (phase A: accS and accT from the same z tile)
template <int KSTEPS, int NT, int BKS>
__device__ __forceinline__ void gemm_dual(uint32_t aA,
                                          uint32_t bA1, uint32_t bAo1,
                                          uint32_t bA2, uint32_t bAo2,
                                          float c1[][4], float c2[][4]) {
#pragma unroll
    for (int ks = 0; ks < KSTEPS; ks++) {
        uint32_t a[4];
        ldsm4(aA, a);
#pragma unroll
        for (int p = 0; p < NT / 2; p++) {
            uint32_t b[4];
            ldsm4(bA1 + p * (16 * BKS * 2), b);
            mma_bf(c1[2 * p],     a, b[0], b[1]);
            mma_bf(c1[2 * p + 1], a, b[2], b[3]);
        }
        if constexpr (NT & 1) {
            uint32_t b[2];
            ldsm2(bAo1, b);
            mma_bf(c1[NT - 1], a, b[0], b[1]);
        }
#pragma unroll
        for (int p = 0; p < NT / 2; p++) {
            uint32_t b[4];
            ldsm4(bA2 + p * (16 * BKS * 2), b);
            mma_bf(c2[2 * p],     a, b[0], b[1]);
            mma_bf(c2[2 * p + 1], a, b[2], b[3]);
        }
        if constexpr (NT & 1) {
            uint32_t b[2];
            ldsm2(bAo2, b);
            mma_bf(c2[NT - 1], a, b[0], b[1]);
        }
        aA += 32; bA1 += 32; bAo1 += 32; bA2 += 32; bAo2 += 32;
    }
}

// relu(c + bias) -> bf16x2 -> hb (word stride 60)
template <int NT>
__device__ __forceinline__ void store_h(const float c[][4], const float* __restrict__ bias,
                                        uint32_t* __restrict__ hb, int nb, int mrow, int g, int t) {
#pragma unroll
    for (int nt = 0; nt < NT; nt++) {
        int cc = nb + nt * 8 + 2 * t;
        float2 b = *(const float2*)&bias[cc];
#pragma unroll
        for (int h = 0; h < 2; h++) {
            int row = mrow + h * 8 + g;
            float v0 = fmaxf(c[nt][2 * h + 0] + b.x, 0.f);
            float v1 = fmaxf(c[nt][2 * h + 1] + b.y, 0.f);
            __nv_bfloat162 p = __floats2bfloat162_rn(v0, v1);
            hb[row * 60 + (cc >> 1)] = *(uint32_t*)&p;
        }
    }
}

// W1 staging split: LDGs early (latency hides under the phase's GEMM)...
__device__ __forceinline__ void loadW1(const float* __restrict__ Wg, float v[W1N], int tid) {
#pragma unroll
    for (int j = 0; j < W1N; j++) {
        int idx = tid + j * NTH;
        v[j] = (idx < KD * NH) ? Wg[idx] : 0.f;
    }
}
// ...convert+scatter to [104 n][72 k-stride halves] bf16 (pads pre-zeroed)
__device__ __forceinline__ void scatW1(const float v[W1N], __nv_bfloat16* __restrict__ dst, int tid) {
#pragma unroll
    for (int j = 0; j < W1N; j++) {
        int idx = tid + j * NTH;
        if (idx < KD * NH) {
            int kk = idx / NH, n = idx - kk * NH;
            dst[n * W1KS + kk] = __float2bfloat16(v[j]);
        }
    }
}

__global__ void __launch_bounds__(NTH, 1) flow_bf16(
    const float* __restrict__ e,
    const float* __restrict__ sW1, const float* __restrict__ sb1,
    const float* __restrict__ sW2, const float* __restrict__ sb2,
    const float* __restrict__ sW3, const float* __restrict__ sb3,
    const float* __restrict__ tW1, const float* __restrict__ tb1,
    const float* __restrict__ tW2, const float* __restrict__ tb2,
    const float* __restrict__ tW3, const float* __restrict__ tb3,
    float* __restrict__ zout, float* __restrict__ ldout)
{
    extern __shared__ float smf[];
    uint32_t* smu = (uint32_t*)smf;
    __nv_bfloat16* smh = (__nv_bfloat16*)smf;

    const int tid = threadIdx.x;
    const int lane = tid & 31, wid = tid >> 5;
    const int g = lane >> 2, t = lane & 3;
    const int mw = wid & 7, nw = wid >> 3;   // 8 m-warps x 2 n-groups
    const int mrow = mw * 16;
    const int nb2 = nw * 56;   // GEMM1/2: nw0 -> 7 n-tiles @0, nw1 -> 6 n-tiles @56
    const int nb3 = nw * 32;   // GEMM3: 4 n-tiles each
    const int pairBar = 1 + mw;
    const long rowBase = (long)blockIdx.x * TB;

    // ---- preload: zero everything below biases (weight pads + H pads + ZB) ----
    for (int w = tid; w < O_B1S; w += NTH) smu[w] = 0u;
    __syncthreads();
    for (int idx = tid; idx < NH * NH; idx += NTH) {
        int in = idx / NH, out = idx - in * NH;
        smh[O_W2S * 2 + out * WKS + in] = __float2bfloat16(sW2[idx]);
        smh[O_W2T * 2 + out * WKS + in] = __float2bfloat16(tW2[idx]);
    }
    for (int idx = tid; idx < NH * KD; idx += NTH) {
        int in = idx / KD, out = idx - in * KD;
        smh[O_W3S * 2 + out * WKS + in] = __float2bfloat16(sW3[idx]);
        smh[O_W3T * 2 + out * WKS + in] = __float2bfloat16(tW3[idx]);
    }
    for (int idx = tid; idx < NPADK; idx += NTH) {
        smf[O_B1S + idx] = (idx < NH) ? sb1[idx] : 0.f;
        smf[O_B2S + idx] = (idx < NH) ? sb2[idx] : 0.f;
        smf[O_B1T + idx] = (idx < NH) ? tb1[idx] : 0.f;
        smf[O_B2T + idx] = (idx < NH) ? tb2[idx] : 0.f;
    }
    for (int idx = tid; idx < KD; idx += NTH) {
        smf[O_B3S + idx] = sb3[idx];
        smf[O_B3T + idx] = tb3[idx];
    }

    // ---- ldmatrix address precompute ----
    const uint32_t smb = sm_u32(smf);
    const int aRow = lane & 15, aK = (lane >> 4) << 3;
    const uint32_t aHB1 = smb + O_HB1 * 4 + ((mrow + aRow) * WKS + aK) * 2;
    const uint32_t aHB2 = smb + O_HB2 * 4 + ((mrow + aRow) * WKS + aK) * 2;
    const uint32_t aZB  = smb + O_ZB  * 4 + ((mrow + aRow) * ZBS + aK) * 2;
    const int bRow  = (lane & 7) + ((lane >> 4) << 3);
    const int bK    = ((lane >> 3) & 1) << 3;
    const int bORow = lane & 7;
    const uint32_t bW2S  = smb + O_W2S * 4 + ((nb2 + bRow) * WKS + bK) * 2;
    const uint32_t bW2So = smb + O_W2S * 4 + ((48 + bORow) * WKS + bK) * 2;   // nw0 tail only
    const uint32_t bW2T  = smb + O_W2T * 4 + ((nb2 + bRow) * WKS + bK) * 2;
    const uint32_t bW2To = smb + O_W2T * 4 + ((48 + bORow) * WKS + bK) * 2;
    const uint32_t bW3S  = smb + O_W3S * 4 + ((nb3 + bRow) * WKS + bK) * 2;
    const uint32_t bW3T  = smb + O_W3T * 4 + ((nb3 + bRow) * WKS + bK) * 2;
    const uint32_t bW1S  = smb + O_W1S0 * 4 + ((nb2 + bRow) * W1KS + bK) * 2;
    const uint32_t bW1So = smb + O_W1S0 * 4 + ((48 + bORow) * W1KS + bK) * 2; // nw0 tail only
    const uint32_t bW1T  = smb + O_W1T0 * 4 + ((nb2 + bRow) * W1KS + bK) * 2;
    const uint32_t bW1To = smb + O_W1T0 * 4 + ((48 + bORow) * W1KS + bK) * 2;

    // persistent layer-1 accumulators (nw0 uses 7 tiles, nw1 uses 6)
    float accS[7][4], accT[7][4];
#pragma unroll
    for (int b = 0; b < 7; b++)
#pragma unroll
        for (int q = 0; q < 4; q++) { accS[b][q] = 0.f; accT[b][q] = 0.f; }
    float ldacc[2] = {0.f, 0.f};

    __syncthreads();

    // Per step: 4 pair-barriers + 1 full sync (step-end). All activation buffers
    // (HB1/HB2/ZB) are pair-local (A-operands/stores touch own m-tile rows only).
    // W1 slice buffers are double-buffered by step parity, so staging (all-thread
    // writes) never collides with current-step readers; the step-end full sync
    // publishes the newly staged parity for the next step.
    for (int i = 0; i < DIMS; i++) {
        const uint32_t rOff = (uint32_t)(((i + 1) & 1) * W1PARB);  // read parity
        const uint32_t wHalf = (uint32_t)((i & 1) * W1PARH);       // write parity (halves)

        // ---- A: acc += z_{i-1} @ W1[i-1] (dual, shared A-frags); h1s -> HB1 ----
        if (i > 0) {
            if (nw == 0)
                gemm_dual<4, 7, W1KS>(aZB, bW1S + rOff, bW1So + rOff,
                                      bW1T + rOff, bW1To + rOff, accS, accT);
            else
                gemm_dual<4, 6, W1KS>(aZB, bW1S + rOff, 0, bW1T + rOff, 0, accS, accT);
        }
        if (nw == 0) store_h<7>(accS, smf + O_B1S, smu + O_HB1, nb2, mrow, g, t);
        else         store_h<6>(accS, smf + O_B1S, smu + O_HB1, nb2, mrow, g, t);
        bar_pair(pairBar);

        // ---- B: GEMM2-s ----
        if (nw == 0) {
            float D[7][4] = {};
            gemm1m<7, 7, WKS>(aHB1, bW2S, bW2So, D);
            store_h<7>(D, smf + O_B2S, smu + O_HB2, nb2, mrow, g, t);
        } else {
            float D[6][4] = {};
            gemm1m<7, 6, WKS>(aHB1, bW2S, 0, D);
            store_h<6>(D, smf + O_B2S, smu + O_HB2, nb2, mrow, g, t);
        }
        bar_pair(pairBar);

        // ---- C: GEMM3-s -> sv (regs) + logdet; h1t -> HB1 ----
        float sv[4][4];
        {
            float Ds[4][4] = {};
            gemm1m<7, 4, WKS>(aHB2, bW3S, 0, Ds);
#pragma unroll
            for (int nt = 0; nt < 4; nt++) {
                int cc = nb3 + nt * 8 + 2 * t;
                float2 b3 = *(const float2*)&smf[O_B3S + cc];
#pragma unroll
                for (int h = 0; h < 2; h++) {
                    float v0 = sigm(Ds[nt][2 * h + 0] + b3.x);
                    float v1 = sigm(Ds[nt][2 * h + 1] + b3.y);
                    sv[nt][2 * h + 0] = v0;
                    sv[nt][2 * h + 1] = v1;
                    ldacc[h] += v0 + v1;
                }
            }
            if (nw == 0) store_h<7>(accT, smf + O_B1T, smu + O_HB1, nb2, mrow, g, t);
            else         store_h<6>(accT, smf + O_B1T, smu + O_HB1, nb2, mrow, g, t);
        }
        bar_pair(pairBar);

        // ---- D: W1s LDGs early; GEMM2-t; scatter W1s into write-parity buffer ----
        {
            float w1v[W1N];
            if (i < DIMS - 1) loadW1(sW1 + (size_t)i * KD * NH, w1v, tid);
            if (nw == 0) {
                float D[7][4] = {};
                gemm1m<7, 7, WKS>(aHB1, bW2T, bW2To, D);
                store_h<7>(D, smf + O_B2T, smu + O_HB2, nb2, mrow, g, t);
            } else {
                float D[6][4] = {};
                gemm1m<7, 6, WKS>(aHB1, bW2T, 0, D);
                store_h<6>(D, smf + O_B2T, smu + O_HB2, nb2, mrow, g, t);
            }
            if (i < DIMS - 1) scatW1(w1v, smh + O_W1S0 * 2 + wHalf, tid);
        }
        bar_pair(pairBar);

        // ---- E: prefetch e; GEMM3-t; epilogue; stage W1t (after epilogue) ----
        {
            float2 eV[8];
#pragma unroll
            for (int nt = 0; nt < 4; nt++)
#pragma unroll
                for (int h = 0; h < 2; h++) {
                    int row = mrow + h * 8 + g;
                    eV[nt * 2 + h] = *(const float2*)&e[(rowBase + row) * TOT + i * KD + nb3 + nt * 8 + 2 * t];
                }

            float Dt[4][4] = {};
            gemm1m<7, 4, WKS>(aHB2, bW3T, 0, Dt);
#pragma unroll
            for (int nt = 0; nt < 4; nt++) {
                int cc = nb3 + nt * 8 + 2 * t;
                float2 b3 = *(const float2*)&smf[O_B3T + cc];
#pragma unroll
                for (int h = 0; h < 2; h++) {
                    int row = mrow + h * 8 + g;
                    long gidx = (rowBase + row) * TOT + i * KD + cc;
                    float t0 = sigm(Dt[nt][2 * h + 0] + b3.x);
                    float t1 = sigm(Dt[nt][2 * h + 1] + b3.y);
                    float2 e2 = eV[nt * 2 + h];
                    float z0 = __expf(sv[nt][2 * h + 0]) * e2.x + t0;
                    float z1 = __expf(sv[nt][2 * h + 1]) * e2.y + t1;
                    *(float2*)&zout[gidx] = make_float2(z0, z1);
                    __nv_bfloat162 zb = __floats2bfloat162_rn(z0, z1);
                    smu[O_ZB + row * 36 + (cc >> 1)] = *(uint32_t*)&zb;
                }
            }
            if (i < DIMS - 1) {
                float w1v[W1N];
                loadW1(tW1 + (size_t)i * KD * NH, w1v, tid);
                scatW1(w1v, smh + O_W1T0 * 2 + wHalf, tid);
            }
        }
        __syncthreads();
    }

    // ---- logdet reduction (scratch aliased over ZB, dead now) ----
#pragma unroll
    for (int h = 0; h < 2; h++) {
        int row = mrow + h * 8 + g;
        smf[O_LDP + row * 8 + nw * 4 + t] = ldacc[h];
    }
    __syncthreads();
    if (tid < TB) {
        float v = 0.f;
#pragma unroll
        for (int q = 0; q < 8; q++) v += smf[O_LDP + tid * 8 + q];
        ldout[rowBase + tid] = v;
    }
}

extern "C" void kernel_launch(void* const* d_in, const int* in_sizes, int n_in,
                              void* d_out, int out_size) {
    const float* e   = (const float*)d_in[0];
    // d_in[1] = C (strictly upper-triangular DAG -> incremental layer-1 acc is exact)
    const float* sW1 = (const float*)d_in[2];
    const float* sb1 = (const float*)d_in[3];
    const float* sW2 = (const float*)d_in[4];
    const float* sb2 = (const float*)d_in[5];
    const float* sW3 = (const float*)d_in[6];
    const float* sb3 = (const float*)d_in[7];
    const float* tW1 = (const float*)d_in[8];
    const float* tb1 = (const float*)d_in[9];
    const float* tW2 = (const float*)d_in[10];
    const float* tb2 = (const float*)d_in[11];
    const float* tW3 = (const float*)d_in[12];
    const float* tb3 = (const float*)d_in[13];

    float* out = (float*)d_out;
    const int B = in_sizes[0] / TOT;
    float* zout  = out;
    float* ldout = out + (size_t)B * TOT;

    cudaFuncSetAttribute(flow_bf16, cudaFuncAttributeMaxDynamicSharedMemorySize,
                         SMW * (int)sizeof(float));

    flow_bf16<<<B / TB, NTH, SMW * sizeof(float)>>>(
        e, sW1, sb1, sW2, sb2, sW3, sb3,
        tW1, tb1, tW2, tb2, tW3, tb3,
        zout, ldout);
}

// round 10
// speedup vs baseline: 1.2754x; 1.0558x over previous
#include <cuda_runtime.h>
#include <cuda_bf16.h>
#include <cstdint>

#define NTH 512
constexpr int TB    = 128;
constexpr int NH    = 100;
constexpr int NPADK = 112;  // k-dim padding (7 k16-steps)
constexpr int NPADN = 104;  // n-dim rows for W2/W1 buffers (13 n8-tiles, 7/6 split)
constexpr int KD    = 64;
constexpr int DIMS  = 8;
constexpr int TOT   = 512;
constexpr int WKS   = 120;  // halves: k-stride for W2/W3/H buffers (conflict-free ldmatrix)
constexpr int W1KS  = 72;   // halves: W1 slice k-stride
constexpr int ZBS   = 72;   // halves: z-buffer stride
constexpr int W1N   = 13;   // ceil(KD*NH / NTH) regs for W1 prefetch
constexpr int W1PARB = 3744 * 4;  // parity offset, bytes
constexpr int W1PARH = 3744 * 2;  // parity offset, halves

// shared layout (word offsets)
constexpr int O_W2S  = 0;                      // [104][60w]
constexpr int O_W2T  = O_W2S + NPADN * 60;     // 6240
constexpr int O_W3S  = O_W2T + NPADN * 60;     // 12480 [64][60w]
constexpr int O_W3T  = O_W3S + 64 * 60;        // 16320
constexpr int O_W1S0 = O_W3T + 64 * 60;        // 20160 [104][36w] x2 parity
constexpr int O_W1T0 = O_W1S0 + 2 * NPADN * 36;// 27648 [104][36w] x2 parity
constexpr int O_HB1  = O_W1T0 + 2 * NPADN * 36;// 35136 [128][60w]
constexpr int O_HB2  = O_HB1 + TB * 60;        // 42816 [128][60w]
constexpr int O_ZB   = O_HB2 + TB * 60;        // 50496 [128][36w] bf16 z (post-loop: logdet scratch)
constexpr int O_LDP  = O_ZB;                   // alias (ZB dead after last step's phase A)
constexpr int O_B1S  = O_ZB + TB * 36;         // 55104
constexpr int O_B2S  = O_B1S + NPADK;
constexpr int O_B3S  = O_B2S + NPADK;
constexpr int O_B1T  = O_B3S + KD;
constexpr int O_B2T  = O_B1T + NPADK;
constexpr int O_B3T  = O_B2T + NPADK;
constexpr int SMW    = O_B3T + KD;             // 55680 words = 222720 B

// sigmoid via tanh.approx: 1 MUFU + 2 FMA (vs ex2 + rcp = 2 MUFU)
__device__ __forceinline__ float sigm(float x) {
    float th;
    asm("tanh.approx.f32 %0, %1;" : "=f"(th) : "f"(x * 0.5f));
    return fmaf(0.5f, th, 0.5f);
}

__device__ __forceinline__ uint32_t sm_u32(const void* p) {
    uint32_t a;
    asm("{ .reg .u64 t; cvta.to.shared.u64 t, %1; cvt.u32.u64 %0, t; }" : "=r"(a) : "l"(p));
    return a;
}

// 64-thread named barrier for the two warps sharing an m-tile
__device__ __forceinline__ void bar_pair(int id) {
    asm volatile("bar.sync %0, 64;" :: "r"(id) : "memory");
}

__device__ __forceinline__ void ldsm4(uint32_t a, uint32_t r[4]) {
    asm volatile("ldmatrix.sync.aligned.m8n8.x4.shared.b16 {%0,%1,%2,%3},[%4];"
                 : "=r"(r[0]), "=r"(r[1]), "=r"(r[2]), "=r"(r[3]) : "r"(a));
}
__device__ __forceinline__ void ldsm2(uint32_t a, uint32_t r[2]) {
    asm volatile("ldmatrix.sync.aligned.m8n8.x2.shared.b16 {%0,%1},[%2];"
                 : "=r"(r[0]), "=r"(r[1]) : "r"(a));
}

__device__ __forceinline__ void mma_bf(float* c, const uint32_t* a, uint32_t b0, uint32_t b1) {
    asm volatile(
        "mma.sync.aligned.m16n8k16.row.col.f32.bf16.bf16.f32 "
        "{%0,%1,%2,%3},{%4,%5,%6,%7},{%8,%9},{%0,%1,%2,%3};"
        : "+f"(c[0]), "+f"(c[1]), "+f"(c[2]), "+f"(c[3])
        : "r"(a[0]), "r"(a[1]), "r"(a[2]), "r"(a[3]), "r"(b0), "r"(b1));
}

// C[NT n8] (+)= A[m16 x 16*KSTEPS] @ B; one m-tile per warp.
template <int KSTEPS, int NT, int BKS>
__device__ __forceinline__ void gemm1m(uint32_t aA, uint32_t bA, uint32_t bAo,
                                       float c[][4]) {
#pragma unroll
    for (int ks = 0; ks < KSTEPS; ks++) {
        uint32_t a[4];
        ldsm4(aA, a);
#pragma unroll
        for (int p = 0; p < NT / 2; p++) {
            uint32_t b[4];
            ldsm4(bA + p * (16 * BKS * 2), b);
            mma_bf(c[2 * p],     a, b[0], b[1]);
            mma_bf(c[2 * p + 1], a, b[2], b[3]);
        }
        if constexpr (NT & 1) {
            uint32_t b[2];
            ldsm2(bAo, b);
            mma_bf(c[NT - 1], a, b[0], b[1]);
        }
        aA += 32; bA += 32; bAo += 32;
    }
}

// Dual-B gemm sharing A-fragments (phase A: accS and accT from the same z tile)
template <int KSTEPS, int NT, int BKS>
__device__ __forceinline__ void gemm_dual(uint32_t aA,
                                          uint32_t bA1, uint32_t bAo1,
                                          uint32_t bA2, uint32_t bAo2,
                                          float c1[][4], float c2[][4]) {
#pragma unroll
    for (int ks = 0; ks < KSTEPS; ks++) {
        uint32_t a[4];
        ldsm4(aA, a);
#pragma unroll
        for (int p = 0; p < NT / 2; p++) {
            uint32_t b[4];
            ldsm4(bA1 + p * (16 * BKS * 2), b);
            mma_bf(c1[2 * p],     a, b[0], b[1]);
            mma_bf(c1[2 * p + 1], a, b[2], b[3]);
        }
        if constexpr (NT & 1) {
            uint32_t b[2];
            ldsm2(bAo1, b);
            mma_bf(c1[NT - 1], a, b[0], b[1]);
        }
#pragma unroll
        for (int p = 0; p < NT / 2; p++) {
            uint32_t b[4];
            ldsm4(bA2 + p * (16 * BKS * 2), b);
            mma_bf(c2[2 * p],     a, b[0], b[1]);
            mma_bf(c2[2 * p + 1], a, b[2], b[3]);
        }
        if constexpr (NT & 1) {
            uint32_t b[2];
            ldsm2(bAo2, b);
            mma_bf(c2[NT - 1], a, b[0], b[1]);
        }
        aA += 32; bA1 += 32; bAo1 += 32; bA2 += 32; bAo2 += 32;
    }
}

// relu(c + bias) -> bf16x2 -> hb (word stride 60)
template <int NT>
__device__ __forceinline__ void store_h(const float c[][4], const float* __restrict__ bias,
                                        uint32_t* __restrict__ hb, int nb, int mrow, int g, int t) {
#pragma unroll
    for (int nt = 0; nt < NT; nt++) {
        int cc = nb + nt * 8 + 2 * t;
        float2 b = *(const float2*)&bias[cc];
#pragma unroll
        for (int h = 0; h < 2; h++) {
            int row = mrow + h * 8 + g;
            float v0 = fmaxf(c[nt][2 * h + 0] + b.x, 0.f);
            float v1 = fmaxf(c[nt][2 * h + 1] + b.y, 0.f);
            __nv_bfloat162 p = __floats2bfloat162_rn(v0, v1);
            hb[row * 60 + (cc >> 1)] = *(uint32_t*)&p;
        }
    }
}

// W1 staging split: LDGs early (latency hides under the phase's GEMM)...
__device__ __forceinline__ void loadW1(const float* __restrict__ Wg, float v[W1N], int tid) {
#pragma unroll
    for (int j = 0; j < W1N; j++) {
        int idx = tid + j * NTH;
        v[j] = (idx < KD * NH) ? Wg[idx] : 0.f;
    }
}
// ...convert+scatter to [104 n][72 k-stride halves] bf16 (pads pre-zeroed)
__device__ __forceinline__ void scatW1(const float v[W1N], __nv_bfloat16* __restrict__ dst, int tid) {
#pragma unroll
    for (int j = 0; j < W1N; j++) {
        int idx = tid + j * NTH;
        if (idx < KD * NH) {
            int kk = idx / NH, n = idx - kk * NH;
            dst[n * W1KS + kk] = __float2bfloat16(v[j]);
        }
    }
}

__global__ void __launch_bounds__(NTH, 1) flow_bf16(
    const float* __restrict__ e,
    const float* __restrict__ sW1, const float* __restrict__ sb1,
    const float* __restrict__ sW2, const float* __restrict__ sb2,
    const float* __restrict__ sW3, const float* __restrict__ sb3,
    const float* __restrict__ tW1, const float* __restrict__ tb1,
    const float* __restrict__ tW2, const float* __restrict__ tb2,
    const float* __restrict__ tW3, const float* __restrict__ tb3,
    float* __restrict__ zout, float* __restrict__ ldout)
{
    extern __shared__ float smf[];
    uint32_t* smu = (uint32_t*)smf;
    __nv_bfloat16* smh = (__nv_bfloat16*)smf;

    const int tid = threadIdx.x;
    const int lane = tid & 31, wid = tid >> 5;
    const int g = lane >> 2, t = lane & 3;
    const int mw = wid & 7, nw = wid >> 3;   // 8 m-warps x 2 n-groups
    const int mrow = mw * 16;
    const int nb2 = nw * 56;   // GEMM1/2: nw0 -> 7 n-tiles @0, nw1 -> 6 n-tiles @56
    const int nb3 = nw * 32;   // GEMM3: 4 n-tiles each
    const int pairBar = 1 + mw;
    const long rowBase = (long)blockIdx.x * TB;

    // hoisted global row pointers (epilogue addresses become base + small offset)
    const float* eR0 = e    + (rowBase + mrow + g)     * TOT + nb3 + 2 * t;
    const float* eR1 = e    + (rowBase + mrow + 8 + g) * TOT + nb3 + 2 * t;
    float*       zR0 = zout + (rowBase + mrow + g)     * TOT + nb3 + 2 * t;
    float*       zR1 = zout + (rowBase + mrow + 8 + g) * TOT + nb3 + 2 * t;

    // ---- preload: zero everything below biases (weight pads + H pads + ZB) ----
    for (int w = tid; w < O_B1S; w += NTH) smu[w] = 0u;
    __syncthreads();
    for (int idx = tid; idx < NH * NH; idx += NTH) {
        int in = idx / NH, out = idx - in * NH;
        smh[O_W2S * 2 + out * WKS + in] = __float2bfloat16(sW2[idx]);
        smh[O_W2T * 2 + out * WKS + in] = __float2bfloat16(tW2[idx]);
    }
    for (int idx = tid; idx < NH * KD; idx += NTH) {
        int in = idx / KD, out = idx - in * KD;
        smh[O_W3S * 2 + out * WKS + in] = __float2bfloat16(sW3[idx]);
        smh[O_W3T * 2 + out * WKS + in] = __float2bfloat16(tW3[idx]);
    }
    for (int idx = tid; idx < NPADK; idx += NTH) {
        smf[O_B1S + idx] = (idx < NH) ? sb1[idx] : 0.f;
        smf[O_B2S + idx] = (idx < NH) ? sb2[idx] : 0.f;
        smf[O_B1T + idx] = (idx < NH) ? tb1[idx] : 0.f;
        smf[O_B2T + idx] = (idx < NH) ? tb2[idx] : 0.f;
    }
    for (int idx = tid; idx < KD; idx += NTH) {
        smf[O_B3S + idx] = sb3[idx];
        smf[O_B3T + idx] = tb3[idx];
    }

    // ---- ldmatrix address precompute ----
    const uint32_t smb = sm_u32(smf);
    const int aRow = lane & 15, aK = (lane >> 4) << 3;
    const uint32_t aHB1 = smb + O_HB1 * 4 + ((mrow + aRow) * WKS + aK) * 2;
    const uint32_t aHB2 = smb + O_HB2 * 4 + ((mrow + aRow) * WKS + aK) * 2;
    const uint32_t aZB  = smb + O_ZB  * 4 + ((mrow + aRow) * ZBS + aK) * 2;
    const int bRow  = (lane & 7) + ((lane >> 4) << 3);
    const int bK    = ((lane >> 3) & 1) << 3;
    const int bORow = lane & 7;
    const uint32_t bW2S  = smb + O_W2S * 4 + ((nb2 + bRow) * WKS + bK) * 2;
    const uint32_t bW2So = smb + O_W2S * 4 + ((48 + bORow) * WKS + bK) * 2;   // nw0 tail only
    const uint32_t bW2T  = smb + O_W2T * 4 + ((nb2 + bRow) * WKS + bK) * 2;
    const uint32_t bW2To = smb + O_W2T * 4 + ((48 + bORow) * WKS + bK) * 2;
    const uint32_t bW3S  = smb + O_W3S * 4 + ((nb3 + bRow) * WKS + bK) * 2;
    const uint32_t bW3T  = smb + O_W3T * 4 + ((nb3 + bRow) * WKS + bK) * 2;
    const uint32_t bW1S  = smb + O_W1S0 * 4 + ((nb2 + bRow) * W1KS + bK) * 2;
    const uint32_t bW1So = smb + O_W1S0 * 4 + ((48 + bORow) * W1KS + bK) * 2; // nw0 tail only
    const uint32_t bW1T  = smb + O_W1T0 * 4 + ((nb2 + bRow) * W1KS + bK) * 2;
    const uint32_t bW1To = smb + O_W1T0 * 4 + ((48 + bORow) * W1KS + bK) * 2;

    // persistent layer-1 accumulators (nw0 uses 7 tiles, nw1 uses 6)
    float accS[7][4], accT[7][4];
#pragma unroll
    for (int b = 0; b < 7; b++)
#pragma unroll
        for (int q = 0; q < 4; q++) { accS[b][q] = 0.f; accT[b][q] = 0.f; }
    float ldacc[2] = {0.f, 0.f};

    __syncthreads();

    // Per step: 4 pair-barriers + 1 full sync. Activation buffers are pair-local;
    // W1 buffers double-buffered by step parity; step-end full sync publishes staging.
    for (int i = 0; i < DIMS; i++) {
        const uint32_t rOff = (uint32_t)(((i + 1) & 1) * W1PARB);  // read parity
        const uint32_t wHalf = (uint32_t)((i & 1) * W1PARH);       // write parity (halves)

        // ---- A: acc += z_{i-1} @ W1[i-1] (dual, shared A-frags); h1s -> HB1 ----
        if (i > 0) {
            if (nw == 0)
                gemm_dual<4, 7, W1KS>(aZB, bW1S + rOff, bW1So + rOff,
                                      bW1T + rOff, bW1To + rOff, accS, accT);
            else
                gemm_dual<4, 6, W1KS>(aZB, bW1S + rOff, 0, bW1T + rOff, 0, accS, accT);
        }
        if (nw == 0) store_h<7>(accS, smf + O_B1S, smu + O_HB1, nb2, mrow, g, t);
        else         store_h<6>(accS, smf + O_B1S, smu + O_HB1, nb2, mrow, g, t);
        bar_pair(pairBar);

        // ---- B: GEMM2-s ----
        if (nw == 0) {
            float D[7][4] = {};
            gemm1m<7, 7, WKS>(aHB1, bW2S, bW2So, D);
            store_h<7>(D, smf + O_B2S, smu + O_HB2, nb2, mrow, g, t);
        } else {
            float D[6][4] = {};
            gemm1m<7, 6, WKS>(aHB1, bW2S, 0, D);
            store_h<6>(D, smf + O_B2S, smu + O_HB2, nb2, mrow, g, t);
        }
        bar_pair(pairBar);

        // ---- C: GEMM3-s -> sv (regs) + logdet; h1t -> HB1 ----
        float sv[4][4];
        {
            float Ds[4][4] = {};
            gemm1m<7, 4, WKS>(aHB2, bW3S, 0, Ds);
#pragma unroll
            for (int nt = 0; nt < 4; nt++) {
                int cc = nb3 + nt * 8 + 2 * t;
                float2 b3 = *(const float2*)&smf[O_B3S + cc];
#pragma unroll
                for (int h = 0; h < 2; h++) {
                    float v0 = sigm(Ds[nt][2 * h + 0] + b3.x);
                    float v1 = sigm(Ds[nt][2 * h + 1] + b3.y);
                    sv[nt][2 * h + 0] = v0;
                    sv[nt][2 * h + 1] = v1;
                    ldacc[h] += v0 + v1;
                }
            }
            if (nw == 0) store_h<7>(accT, smf + O_B1T, smu + O_HB1, nb2, mrow, g, t);
            else         store_h<6>(accT, smf + O_B1T, smu + O_HB1, nb2, mrow, g, t);
        }
        bar_pair(pairBar);

        // ---- D: W1s LDGs early; GEMM2-t; scatter W1s into write-parity buffer ----
        {
            float w1v[W1N];
            if (i < DIMS - 1) loadW1(sW1 + (size_t)i * KD * NH, w1v, tid);
            if (nw == 0) {
                float D[7][4] = {};
                gemm1m<7, 7, WKS>(aHB1, bW2T, bW2To, D);
                store_h<7>(D, smf + O_B2T, smu + O_HB2, nb2, mrow, g, t);
            } else {
                float D[6][4] = {};
                gemm1m<7, 6, WKS>(aHB1, bW2T, 0, D);
                store_h<6>(D, smf + O_B2T, smu + O_HB2, nb2, mrow, g, t);
            }
            if (i < DIMS - 1) scatW1(w1v, smh + O_W1S0 * 2 + wHalf, tid);
        }
        bar_pair(pairBar);

        // ---- E: prefetch e; GEMM3-t; epilogue; stage W1t (after epilogue) ----
        {
            const int eoff = i * KD;
            float2 eV[8];
#pragma unroll
            for (int nt = 0; nt < 4; nt++) {
                eV[nt * 2 + 0] = *(const float2*)&eR0[eoff + nt * 8];
                eV[nt * 2 + 1] = *(const float2*)&eR1[eoff + nt * 8];
            }

            float Dt[4][4] = {};
            gemm1m<7, 4, WKS>(aHB2, bW3T, 0, Dt);
#pragma unroll
            for (int nt = 0; nt < 4; nt++) {
                int cc = nb3 + nt * 8 + 2 * t;
                float2 b3 = *(const float2*)&smf[O_B3T + cc];
#pragma unroll
                for (int h = 0; h < 2; h++) {
                    int row = mrow + h * 8 + g;
                    float t0 = sigm(Dt[nt][2 * h + 0] + b3.x);
                    float t1 = sigm(Dt[nt][2 * h + 1] + b3.y);
                    float2 e2 = eV[nt * 2 + h];
                    float z0 = __expf(sv[nt][2 * h + 0]) * e2.x + t0;
                    float z1 = __expf(sv[nt][2 * h + 1]) * e2.y + t1;
                    float* zp = (h == 0) ? (zR0 + eoff + nt * 8) : (zR1 + eoff + nt * 8);
                    *(float2*)zp = make_float2(z0, z1);
                    __nv_bfloat162 zb = __floats2bfloat162_rn(z0, z1);
                    smu[O_ZB + row * 36 + (cc >> 1)] = *(uint32_t*)&zb;
                }
            }
            if (i < DIMS - 1) {
                float w1v[W1N];
                loadW1(tW1 + (size_t)i * KD * NH, w1v, tid);
                scatW1(w1v, smh + O_W1T0 * 2 + wHalf, tid);
            }
        }
        __syncthreads();
    }

    // ---- logdet reduction (scratch aliased over ZB, dead now) ----
#pragma unroll
    for (int h = 0; h < 2; h++) {
        int row = mrow + h * 8 + g;
        smf[O_LDP + row * 8 + nw * 4 + t] = ldacc[h];
    }
    __syncthreads();
    if (tid < TB) {
        float v = 0.f;
#pragma unroll
        for (int q = 0; q < 8; q++) v += smf[O_LDP + tid * 8 + q];
        ldout[rowBase + tid] = v;
    }
}

extern "C" void kernel_launch(void* const* d_in, const int* in_sizes, int n_in,
                              void* d_out, int out_size) {
    const float* e   = (const float*)d_in[0];
    // d_in[1] = C (strictly upper-triangular DAG -> incremental layer-1 acc is exact)
    const float* sW1 = (const float*)d_in[2];
    const float* sb1 = (const float*)d_in[3];
    const float* sW2 = (const float*)d_in[4];
    const float* sb2 = (const float*)d_in[5];
    const float* sW3 = (const float*)d_in[6];
    const float* sb3 = (const float*)d_in[7];
    const float* tW1 = (const float*)d_in[8];
    const float* tb1 = (const float*)d_in[9];
    const float* tW2 = (const float*)d_in[10];
    const float* tb2 = (const float*)d_in[11];
    const float* tW3 = (const float*)d_in[12];
    const float* tb3 = (const float*)d_in[13];

    float* out = (float*)d_out;
    const int B = in_sizes[0] / TOT;
    float* zout  = out;
    float* ldout = out + (size_t)B * TOT;

    cudaFuncSetAttribute(flow_bf16, cudaFuncAttributeMaxDynamicSharedMemorySize,
                         SMW * (int)sizeof(float));

    flow_bf16<<<B / TB, NTH, SMW * sizeof(float)>>>(
        e, sW1, sb1, sW2, sb2, sW3, sb3,
        tW1, tb1, tW2, tb2, tW3, tb3,
        zout, ldout);
}

// round 11
// speedup vs baseline: 1.3246x; 1.0386x over previous
#include <cuda_runtime.h>
#include <cuda_bf16.h>
#include <cstdint>

#define NTH 512
constexpr int TB    = 128;
constexpr int NH    = 100;
constexpr int NPADK = 112;  // k-dim padding (7 k16-steps)
constexpr int NPADN = 104;  // n-dim rows for W2/W1 buffers (13 n8-tiles, 7/6 split)
constexpr int KD    = 64;
constexpr int DIMS  = 8;
constexpr int TOT   = 512;
constexpr int WKS   = 120;  // halves: k-stride for W2/W3/H buffers (conflict-free ldmatrix)
constexpr int W1KS  = 72;   // halves: W1 slice k-stride
constexpr int ZBS   = 72;   // halves: z-buffer stride
constexpr int W1N   = 13;   // ceil(KD*NH / NTH) regs for W1 prefetch
constexpr int W1PARB = 3744 * 4;  // parity offset, bytes
constexpr int W1PARH = 3744 * 2;  // parity offset, halves

// shared layout (word offsets)
constexpr int O_W2S  = 0;                      // [104][60w]
constexpr int O_W2T  = O_W2S + NPADN * 60;     // 6240
constexpr int O_W3S  = O_W2T + NPADN * 60;     // 12480 [64][60w]
constexpr int O_W3T  = O_W3S + 64 * 60;        // 16320
constexpr int O_W1S0 = O_W3T + 64 * 60;        // 20160 [104][36w] x2 parity
constexpr int O_W1T0 = O_W1S0 + 2 * NPADN * 36;// 27648 [104][36w] x2 parity
constexpr int O_HB1  = O_W1T0 + 2 * NPADN * 36;// 35136 [128][60w]
constexpr int O_HB2  = O_HB1 + TB * 60;        // 42816 [128][60w] (step-0: constant scratch)
constexpr int O_ZB   = O_HB2 + TB * 60;        // 50496 [128][36w] bf16 z (post-loop: logdet scratch)
constexpr int O_LDP  = O_ZB;                   // alias (ZB dead after last step's phase A)
constexpr int O_B1S  = O_ZB + TB * 36;         // 55104
constexpr int O_B2S  = O_B1S + NPADK;
constexpr int O_B3S  = O_B2S + NPADK;
constexpr int O_B1T  = O_B3S + KD;
constexpr int O_B2T  = O_B1T + NPADK;
constexpr int O_B3T  = O_B2T + NPADK;
constexpr int SMW    = O_B3T + KD;             // 55680 words = 222720 B

// step-0 constant scratch (word offsets inside HB2, free at step 0)
constexpr int C_S0  = O_HB2 + 0;    // s0[64] fp32
constexpr int C_T0  = O_HB2 + 64;   // t0[64]
constexpr int C_ES0 = O_HB2 + 128;  // exp(s0)[64]
constexpr int C_H1S = O_HB2 + 192;  // h1s bf16-rounded fp32 [100]
constexpr int C_H1T = O_HB2 + 304;
constexpr int C_H2S = O_HB2 + 416;  // h2s bf16-rounded fp32 [100]
constexpr int C_H2T = O_HB2 + 516;

// sigmoid via tanh.approx: 1 MUFU + 2 FMA
__device__ __forceinline__ float sigm(float x) {
    float th;
    asm("tanh.approx.f32 %0, %1;" : "=f"(th) : "f"(x * 0.5f));
    return fmaf(0.5f, th, 0.5f);
}

__device__ __forceinline__ uint32_t sm_u32(const void* p) {
    uint32_t a;
    asm("{ .reg .u64 t; cvta.to.shared.u64 t, %1; cvt.u32.u64 %0, t; }" : "=r"(a) : "l"(p));
    return a;
}

// 64-thread named barrier for the two warps sharing an m-tile
__device__ __forceinline__ void bar_pair(int id) {
    asm volatile("bar.sync %0, 64;" :: "r"(id) : "memory");
}

__device__ __forceinline__ void ldsm4(uint32_t a, uint32_t r[4]) {
    asm volatile("ldmatrix.sync.aligned.m8n8.x4.shared.b16 {%0,%1,%2,%3},[%4];"
                 : "=r"(r[0]), "=r"(r[1]), "=r"(r[2]), "=r"(r[3]) : "r"(a));
}
__device__ __forceinline__ void ldsm2(uint32_t a, uint32_t r[2]) {
    asm volatile("ldmatrix.sync.aligned.m8n8.x2.shared.b16 {%0,%1},[%2];"
                 : "=r"(r[0]), "=r"(r[1]) : "r"(a));
}

__device__ __forceinline__ void mma_bf(float* c, const uint32_t* a, uint32_t b0, uint32_t b1) {
    asm volatile(
        "mma.sync.aligned.m16n8k16.row.col.f32.bf16.bf16.f32 "
        "{%0,%1,%2,%3},{%4,%5,%6,%7},{%8,%9},{%0,%1,%2,%3};"
        : "+f"(c[0]), "+f"(c[1]), "+f"(c[2]), "+f"(c[3])
        : "r"(a[0]), "r"(a[1]), "r"(a[2]), "r"(a[3]), "r"(b0), "r"(b1));
}

template <int KSTEPS, int NT, int BKS>
__device__ __forceinline__ void gemm1m(uint32_t aA, uint32_t bA, uint32_t bAo,
                                       float c[][4]) {
#pragma unroll
    for (int ks = 0; ks < KSTEPS; ks++) {
        uint32_t a[4];
        ldsm4(aA, a);
#pragma unroll
        for (int p = 0; p < NT / 2; p++) {
            uint32_t b[4];
            ldsm4(bA + p * (16 * BKS * 2), b);
            mma_bf(c[2 * p],     a, b[0], b[1]);
            mma_bf(c[2 * p + 1], a, b[2], b[3]);
        }
        if constexpr (NT & 1) {
            uint32_t b[2];
            ldsm2(bAo, b);
            mma_bf(c[NT - 1], a, b[0], b[1]);
        }
        aA += 32; bA += 32; bAo += 32;
    }
}

template <int KSTEPS, int NT, int BKS>
__device__ __forceinline__ void gemm_dual(uint32_t aA,
                                          uint32_t bA1, uint32_t bAo1,
                                          uint32_t bA2, uint32_t bAo2,
                                          float c1[][4], float c2[][4]) {
#pragma unroll
    for (int ks = 0; ks < KSTEPS; ks++) {
        uint32_t a[4];
        ldsm4(aA, a);
#pragma unroll
        for (int p = 0; p < NT / 2; p++) {
            uint32_t b[4];
            ldsm4(bA1 + p * (16 * BKS * 2), b);
            mma_bf(c1[2 * p],     a, b[0], b[1]);
            mma_bf(c1[2 * p + 1], a, b[2], b[3]);
        }
        if constexpr (NT & 1) {
            uint32_t b[2];
            ldsm2(bAo1, b);
            mma_bf(c1[NT - 1], a, b[0], b[1]);
        }
#pragma unroll
        for (int p = 0; p < NT / 2; p++) {
            uint32_t b[4];
            ldsm4(bA2 + p * (16 * BKS * 2), b);
            mma_bf(c2[2 * p],     a, b[0], b[1]);
            mma_bf(c2[2 * p + 1], a, b[2], b[3]);
        }
        if constexpr (NT & 1) {
            uint32_t b[2];
            ldsm2(bAo2, b);
            mma_bf(c2[NT - 1], a, b[0], b[1]);
        }
        aA += 32; bA1 += 32; bAo1 += 32; bA2 += 32; bAo2 += 32;
    }
}

template <int NT>
__device__ __forceinline__ void store_h(const float c[][4], const float* __restrict__ bias,
                                        uint32_t* __restrict__ hb, int nb, int mrow, int g, int t) {
#pragma unroll
    for (int nt = 0; nt < NT; nt++) {
        int cc = nb + nt * 8 + 2 * t;
        float2 b = *(const float2*)&bias[cc];
#pragma unroll
        for (int h = 0; h < 2; h++) {
            int row = mrow + h * 8 + g;
            float v0 = fmaxf(c[nt][2 * h + 0] + b.x, 0.f);
            float v1 = fmaxf(c[nt][2 * h + 1] + b.y, 0.f);
            __nv_bfloat162 p = __floats2bfloat162_rn(v0, v1);
            hb[row * 60 + (cc >> 1)] = *(uint32_t*)&p;
        }
    }
}

__device__ __forceinline__ void loadW1(const float* __restrict__ Wg, float v[W1N], int tid) {
#pragma unroll
    for (int j = 0; j < W1N; j++) {
        int idx = tid + j * NTH;
        v[j] = (idx < KD * NH) ? Wg[idx] : 0.f;
    }
}
__device__ __forceinline__ void scatW1(const float v[W1N], __nv_bfloat16* __restrict__ dst, int tid) {
#pragma unroll
    for (int j = 0; j < W1N; j++) {
        int idx = tid + j * NTH;
        if (idx < KD * NH) {
            int kk = idx / NH, n = idx - kk * NH;
            dst[n * W1KS + kk] = __float2bfloat16(v[j]);
        }
    }
}

__global__ void __launch_bounds__(NTH, 1) flow_bf16(
    const float* __restrict__ e,
    const float* __restrict__ sW1, const float* __restrict__ sb1,
    const float* __restrict__ sW2, const float* __restrict__ sb2,
    const float* __restrict__ sW3, const float* __restrict__ sb3,
    const float* __restrict__ tW1, const float* __restrict__ tb1,
    const float* __restrict__ tW2, const float* __restrict__ tb2,
    const float* __restrict__ tW3, const float* __restrict__ tb3,
    float* __restrict__ zout, float* __restrict__ ldout)
{
    extern __shared__ float smf[];
    uint32_t* smu = (uint32_t*)smf;
    __nv_bfloat16* smh = (__nv_bfloat16*)smf;

    const int tid = threadIdx.x;
    const int lane = tid & 31, wid = tid >> 5;
    const int g = lane >> 2, t = lane & 3;
    const int mw = wid & 7, nw = wid >> 3;   // 8 m-warps x 2 n-groups
    const int mrow = mw * 16;
    const int nb2 = nw * 56;
    const int nb3 = nw * 32;
    const int pairBar = 1 + mw;
    const long rowBase = (long)blockIdx.x * TB;

    const float* eR0 = e    + (rowBase + mrow + g)     * TOT + nb3 + 2 * t;
    const float* eR1 = e    + (rowBase + mrow + 8 + g) * TOT + nb3 + 2 * t;
    float*       zR0 = zout + (rowBase + mrow + g)     * TOT + nb3 + 2 * t;
    float*       zR1 = zout + (rowBase + mrow + 8 + g) * TOT + nb3 + 2 * t;

    // ---- preload: zero everything below biases, fill transposed bf16 weights ----
    for (int w = tid; w < O_B1S; w += NTH) smu[w] = 0u;
    __syncthreads();
    for (int idx = tid; idx < NH * NH; idx += NTH) {
        int in = idx / NH, out = idx - in * NH;
        smh[O_W2S * 2 + out * WKS + in] = __float2bfloat16(sW2[idx]);
        smh[O_W2T * 2 + out * WKS + in] = __float2bfloat16(tW2[idx]);
    }
    for (int idx = tid; idx < NH * KD; idx += NTH) {
        int in = idx / KD, out = idx - in * KD;
        smh[O_W3S * 2 + out * WKS + in] = __float2bfloat16(sW3[idx]);
        smh[O_W3T * 2 + out * WKS + in] = __float2bfloat16(tW3[idx]);
    }
    for (int idx = tid; idx < NPADK; idx += NTH) {
        smf[O_B1S + idx] = (idx < NH) ? sb1[idx] : 0.f;
        smf[O_B2S + idx] = (idx < NH) ? sb2[idx] : 0.f;
        smf[O_B1T + idx] = (idx < NH) ? tb1[idx] : 0.f;
        smf[O_B2T + idx] = (idx < NH) ? tb2[idx] : 0.f;
    }
    for (int idx = tid; idx < KD; idx += NTH) {
        smf[O_B3S + idx] = sb3[idx];
        smf[O_B3T + idx] = tb3[idx];
    }

    // ---- ldmatrix address precompute ----
    const uint32_t smb = sm_u32(smf);
    const int aRow = lane & 15, aK = (lane >> 4) << 3;
    const uint32_t aHB1 = smb + O_HB1 * 4 + ((mrow + aRow) * WKS + aK) * 2;
    const uint32_t aHB2 = smb + O_HB2 * 4 + ((mrow + aRow) * WKS + aK) * 2;
    const uint32_t aZB  = smb + O_ZB  * 4 + ((mrow + aRow) * ZBS + aK) * 2;
    const int bRow  = (lane & 7) + ((lane >> 4) << 3);
    const int bK    = ((lane >> 3) & 1) << 3;
    const int bORow = lane & 7;
    const uint32_t bW2S  = smb + O_W2S * 4 + ((nb2 + bRow) * WKS + bK) * 2;
    const uint32_t bW2So = smb + O_W2S * 4 + ((48 + bORow) * WKS + bK) * 2;
    const uint32_t bW2T  = smb + O_W2T * 4 + ((nb2 + bRow) * WKS + bK) * 2;
    const uint32_t bW2To = smb + O_W2T * 4 + ((48 + bORow) * WKS + bK) * 2;
    const uint32_t bW3S  = smb + O_W3S * 4 + ((nb3 + bRow) * WKS + bK) * 2;
    const uint32_t bW3T  = smb + O_W3T * 4 + ((nb3 + bRow) * WKS + bK) * 2;
    const uint32_t bW1S  = smb + O_W1S0 * 4 + ((nb2 + bRow) * W1KS + bK) * 2;
    const uint32_t bW1So = smb + O_W1S0 * 4 + ((48 + bORow) * W1KS + bK) * 2;
    const uint32_t bW1T  = smb + O_W1T0 * 4 + ((nb2 + bRow) * W1KS + bK) * 2;
    const uint32_t bW1To = smb + O_W1T0 * 4 + ((48 + bORow) * W1KS + bK) * 2;

    float accS[7][4], accT[7][4];
#pragma unroll
    for (int b = 0; b < 7; b++)
#pragma unroll
        for (int q = 0; q < 4; q++) { accS[b][q] = 0.f; accT[b][q] = 0.f; }
    float ldacc[2] = {0.f, 0.f};

    __syncthreads();

    // ===== STEP 0: MLP inputs are identically zero -> s,t batch-constant =====
    // h1 = relu(b1) (constant), so s0/t0 are 64-vectors shared by all rows.
    // Replaces 4 GEMM phases with two 100x100 + two 100x64 MVs (bf16-rounded
    // activations to match MMA arithmetic exactly).
    {
        if (tid < NH) {
            smf[C_H1S + tid] = __bfloat162float(__float2bfloat16(fmaxf(smf[O_B1S + tid], 0.f)));
            smf[C_H1T + tid] = __bfloat162float(__float2bfloat16(fmaxf(smf[O_B1T + tid], 0.f)));
        }
        __syncthreads();
        if (tid < NH) {
            float d = 0.f;
#pragma unroll 4
            for (int in = 0; in < NH; in++)
                d = fmaf(__bfloat162float(smh[O_W2S * 2 + tid * WKS + in]), smf[C_H1S + in], d);
            smf[C_H2S + tid] = __bfloat162float(__float2bfloat16(fmaxf(d + smf[O_B2S + tid], 0.f)));
        } else if (tid >= 256 && tid < 256 + NH) {
            int o = tid - 256;
            float d = 0.f;
#pragma unroll 4
            for (int in = 0; in < NH; in++)
                d = fmaf(__bfloat162float(smh[O_W2T * 2 + o * WKS + in]), smf[C_H1T + in], d);
            smf[C_H2T + o] = __bfloat162float(__float2bfloat16(fmaxf(d + smf[O_B2T + o], 0.f)));
        }
        __syncthreads();
        if (tid < KD) {
            float d = 0.f;
#pragma unroll 4
            for (int in = 0; in < NH; in++)
                d = fmaf(__bfloat162float(smh[O_W3S * 2 + tid * WKS + in]), smf[C_H2S + in], d);
            float s = sigm(d + smf[O_B3S + tid]);
            smf[C_S0 + tid] = s;
            smf[C_ES0 + tid] = __expf(s);
        } else if (tid >= 256 && tid < 256 + KD) {
            int o = tid - 256;
            float d = 0.f;
#pragma unroll 4
            for (int in = 0; in < NH; in++)
                d = fmaf(__bfloat162float(smh[O_W3T * 2 + o * WKS + in]), smf[C_H2T + in], d);
            smf[C_T0 + o] = sigm(d + smf[O_B3T + o]);
        }
        __syncthreads();
        // step-0 epilogue: z = exp(s0)*e + t0; ZB; logdet; stage W1 slice 0 (parity 0)
        {
            float2 eV[8];
#pragma unroll
            for (int nt = 0; nt < 4; nt++) {
                eV[nt * 2 + 0] = *(const float2*)&eR0[nt * 8];
                eV[nt * 2 + 1] = *(const float2*)&eR1[nt * 8];
            }
            float partial = 0.f;
#pragma unroll
            for (int nt = 0; nt < 4; nt++) {
                int cc = nb3 + nt * 8 + 2 * t;
                float s0a = smf[C_S0 + cc],  s0b = smf[C_S0 + cc + 1];
                float exa = smf[C_ES0 + cc], exb = smf[C_ES0 + cc + 1];
                float t0a = smf[C_T0 + cc],  t0b = smf[C_T0 + cc + 1];
                partial += s0a + s0b;
#pragma unroll
                for (int h = 0; h < 2; h++) {
                    int row = mrow + h * 8 + g;
                    float2 e2 = eV[nt * 2 + h];
                    float z0 = exa * e2.x + t0a;
                    float z1 = exb * e2.y + t0b;
                    float* zp = (h == 0) ? (zR0 + nt * 8) : (zR1 + nt * 8);
                    *(float2*)zp = make_float2(z0, z1);
                    __nv_bfloat162 zb = __floats2bfloat162_rn(z0, z1);
                    smu[O_ZB + row * 36 + (cc >> 1)] = *(uint32_t*)&zb;
                }
            }
            ldacc[0] += partial;
            ldacc[1] += partial;
            float w1v[W1N];
            loadW1(sW1, w1v, tid);
            scatW1(w1v, smh + O_W1S0 * 2, tid);   // parity 0 (read at i=1)
            loadW1(tW1, w1v, tid);
            scatW1(w1v, smh + O_W1T0 * 2, tid);
        }
        __syncthreads();
    }

    // ===== steps 1..7: general MMA path =====
    for (int i = 1; i < DIMS; i++) {
        const uint32_t rOff = (uint32_t)(((i + 1) & 1) * W1PARB);  // read parity
        const uint32_t wHalf = (uint32_t)((i & 1) * W1PARH);       // write parity (halves)

        // ---- A: acc += z_{i-1} @ W1[i-1] (dual, shared A-frags); h1s -> HB1 ----
        if (nw == 0)
            gemm_dual<4, 7, W1KS>(aZB, bW1S + rOff, bW1So + rOff,
                                  bW1T + rOff, bW1To + rOff, accS, accT);
        else
            gemm_dual<4, 6, W1KS>(aZB, bW1S + rOff, 0, bW1T + rOff, 0, accS, accT);
        if (nw == 0) store_h<7>(accS, smf + O_B1S, smu + O_HB1, nb2, mrow, g, t);
        else         store_h<6>(accS, smf + O_B1S, smu + O_HB1, nb2, mrow, g, t);
        bar_pair(pairBar);

        // ---- B: GEMM2-s ----
        if (nw == 0) {
            float D[7][4] = {};
            gemm1m<7, 7, WKS>(aHB1, bW2S, bW2So, D);
            store_h<7>(D, smf + O_B2S, smu + O_HB2, nb2, mrow, g, t);
        } else {
            float D[6][4] = {};
            gemm1m<7, 6, WKS>(aHB1, bW2S, 0, D);
            store_h<6>(D, smf + O_B2S, smu + O_HB2, nb2, mrow, g, t);
        }
        bar_pair(pairBar);

        // ---- C: GEMM3-s -> sv (regs) + logdet; h1t -> HB1 ----
        float sv[4][4];
        {
            float Ds[4][4] = {};
            gemm1m<7, 4, WKS>(aHB2, bW3S, 0, Ds);
#pragma unroll
            for (int nt = 0; nt < 4; nt++) {
                int cc = nb3 + nt * 8 + 2 * t;
                float2 b3 = *(const float2*)&smf[O_B3S + cc];
#pragma unroll
                for (int h = 0; h < 2; h++) {
                    float v0 = sigm(Ds[nt][2 * h + 0] + b3.x);
                    float v1 = sigm(Ds[nt][2 * h + 1] + b3.y);
                    sv[nt][2 * h + 0] = v0;
                    sv[nt][2 * h + 1] = v1;
                    ldacc[h] += v0 + v1;
                }
            }
            if (nw == 0) store_h<7>(accT, smf + O_B1T, smu + O_HB1, nb2, mrow, g, t);
            else         store_h<6>(accT, smf + O_B1T, smu + O_HB1, nb2, mrow, g, t);
        }
        bar_pair(pairBar);

        // ---- D: W1s LDGs early; GEMM2-t; scatter W1s into write-parity buffer ----
        {
            float w1v[W1N];
            if (i < DIMS - 1) loadW1(sW1 + (size_t)i * KD * NH, w1v, tid);
            if (nw == 0) {
                float D[7][4] = {};
                gemm1m<7, 7, WKS>(aHB1, bW2T, bW2To, D);
                store_h<7>(D, smf + O_B2T, smu + O_HB2, nb2, mrow, g, t);
            } else {
                float D[6][4] = {};
                gemm1m<7, 6, WKS>(aHB1, bW2T, 0, D);
                store_h<6>(D, smf + O_B2T, smu + O_HB2, nb2, mrow, g, t);
            }
            if (i < DIMS - 1) scatW1(w1v, smh + O_W1S0 * 2 + wHalf, tid);
        }
        bar_pair(pairBar);

        // ---- E: prefetch e; GEMM3-t; epilogue; stage W1t ----
        {
            const int eoff = i * KD;
            float2 eV[8];
#pragma unroll
            for (int nt = 0; nt < 4; nt++) {
                eV[nt * 2 + 0] = *(const float2*)&eR0[eoff + nt * 8];
                eV[nt * 2 + 1] = *(const float2*)&eR1[eoff + nt * 8];
            }

            float Dt[4][4] = {};
            gemm1m<7, 4, WKS>(aHB2, bW3T, 0, Dt);
#pragma unroll
            for (int nt = 0; nt < 4; nt++) {
                int cc = nb3 + nt * 8 + 2 * t;
                float2 b3 = *(const float2*)&smf[O_B3T + cc];
#pragma unroll
                for (int h = 0; h < 2; h++) {
                    int row = mrow + h * 8 + g;
                    float t0 = sigm(Dt[nt][2 * h + 0] + b3.x);
                    float t1 = sigm(Dt[nt][2 * h + 1] + b3.y);
                    float2 e2 = eV[nt * 2 + h];
                    float z0 = __expf(sv[nt][2 * h + 0]) * e2.x + t0;
                    float z1 = __expf(sv[nt][2 * h + 1]) * e2.y + t1;
                    float* zp = (h == 0) ? (zR0 + eoff + nt * 8) : (zR1 + eoff + nt * 8);
                    *(float2*)zp = make_float2(z0, z1);
                    __nv_bfloat162 zb = __floats2bfloat162_rn(z0, z1);
                    smu[O_ZB + row * 36 + (cc >> 1)] = *(uint32_t*)&zb;
                }
            }
            if (i < DIMS - 1) {
                float w1v[W1N];
                loadW1(tW1 + (size_t)i * KD * NH, w1v, tid);
                scatW1(w1v, smh + O_W1T0 * 2 + wHalf, tid);
            }
        }
        __syncthreads();
    }

    // ---- logdet reduction (scratch aliased over ZB, dead now) ----
#pragma unroll
    for (int h = 0; h < 2; h++) {
        int row = mrow + h * 8 + g;
        smf[O_LDP + row * 8 + nw * 4 + t] = ldacc[h];
    }
    __syncthreads();
    if (tid < TB) {
        float v = 0.f;
#pragma unroll
        for (int q = 0; q < 8; q++) v += smf[O_LDP + tid * 8 + q];
        ldout[rowBase + tid] = v;
    }
}

extern "C" void kernel_launch(void* const* d_in, const int* in_sizes, int n_in,
                              void* d_out, int out_size) {
    const float* e   = (const float*)d_in[0];
    // d_in[1] = C (strictly upper-triangular DAG -> incremental layer-1 acc is exact)
    const float* sW1 = (const float*)d_in[2];
    const float* sb1 = (const float*)d_in[3];
    const float* sW2 = (const float*)d_in[4];
    const float* sb2 = (const float*)d_in[5];
    const float* sW3 = (const float*)d_in[6];
    const float* sb3 = (const float*)d_in[7];
    const float* tW1 = (const float*)d_in[8];
    const float* tb1 = (const float*)d_in[9];
    const float* tW2 = (const float*)d_in[10];
    const float* tb2 = (const float*)d_in[11];
    const float* tW3 = (const float*)d_in[12];
    const float* tb3 = (const float*)d_in[13];

    float* out = (float*)d_out;
    const int B = in_sizes[0] / TOT;
    float* zout  = out;
    float* ldout = out + (size_t)B * TOT;

    cudaFuncSetAttribute(flow_bf16, cudaFuncAttributeMaxDynamicSharedMemorySize,
                         SMW * (int)sizeof(float));

    flow_bf16<<<B / TB, NTH, SMW * sizeof(float)>>>(
        e, sW1, sb1, sW2, sb2, sW3, sb3,
        tW1, tb1, tW2, tb2, tW3, tb3,
        zout, ldout);
}

// round 13
// speedup vs baseline: 1.4234x; 1.0746x over previous
#include <cuda_runtime.h>
#include <cuda_bf16.h>
#include <cstdint>

#define NTH 512
constexpr int TB    = 128;
constexpr int NH    = 100;
constexpr int NPADK = 112;  // k-dim padding (7 k16-steps)
constexpr int KD    = 64;
constexpr int DIMS  = 8;
constexpr int TOT   = 512;
constexpr int WKS   = 120;  // halves: k-stride for W2/W3/H buffers (conflict-free ldmatrix)
constexpr int W1KS  = 72;   // halves: W1 slice k-stride
constexpr int ZBS   = 72;   // halves: z-buffer stride
constexpr int W1N   = 13;   // ceil(KD*NH / NTH) regs for W1 prefetch
constexpr int W1PARB = 3744 * 4;  // parity offset, bytes
constexpr int W1PARH = 3744 * 2;  // parity offset, halves

// shared layout (word offsets)
constexpr int O_W2S  = 0;                      // [104][60w]
constexpr int O_W2T  = O_W2S + 104 * 60;       // 6240
constexpr int O_W3S  = O_W2T + 104 * 60;       // 12480 [64][60w]
constexpr int O_W3T  = O_W3S + 64 * 60;        // 16320
constexpr int O_W1S0 = O_W3T + 64 * 60;        // 20160 [104][36w] x2 parity
constexpr int O_W1T0 = O_W1S0 + 2 * 104 * 36;  // 27648 [104][36w] x2 parity
constexpr int O_HB1  = O_W1T0 + 2 * 104 * 36;  // 35136 [128][60w]
constexpr int O_HB2  = O_HB1 + TB * 60;        // 42816 [128][60w] (step-0: constant scratch)
constexpr int O_ZB   = O_HB2 + TB * 60;        // 50496 [128][36w] bf16 z (post: logdet)
constexpr int O_LDP  = O_ZB;                   // alias
constexpr int O_B1S  = O_ZB + TB * 36;         // 55104
constexpr int O_B2S  = O_B1S + NPADK;
constexpr int O_B3S  = O_B2S + NPADK;
constexpr int O_B1T  = O_B3S + KD;
constexpr int O_B2T  = O_B1T + NPADK;
constexpr int O_B3T  = O_B2T + NPADK;
constexpr int SMW    = O_B3T + KD;             // 55680 words = 222720 B

// step-0 constant scratch (inside HB2, free at step 0)
constexpr int C_S0  = O_HB2 + 0;
constexpr int C_T0  = O_HB2 + 64;
constexpr int C_ES0 = O_HB2 + 128;
constexpr int C_H1S = O_HB2 + 192;
constexpr int C_H1T = O_HB2 + 304;
constexpr int C_H2S = O_HB2 + 416;
constexpr int C_H2T = O_HB2 + 516;

__device__ __forceinline__ float sigm(float x) {
    float th;
    asm("tanh.approx.f32 %0, %1;" : "=f"(th) : "f"(x * 0.5f));
    return fmaf(0.5f, th, 0.5f);
}

__device__ __forceinline__ uint32_t sm_u32(const void* p) {
    uint32_t a;
    asm("{ .reg .u64 t; cvta.to.shared.u64 t, %1; cvt.u32.u64 %0, t; }" : "=r"(a) : "l"(p));
    return a;
}

__device__ __forceinline__ void bar_pair(int id) {
    asm volatile("bar.sync %0, 64;" :: "r"(id) : "memory");
}

__device__ __forceinline__ void prefetchL2(const void* p) {
    asm volatile("prefetch.global.L2 [%0];" :: "l"(p));
}

__device__ __forceinline__ void ldsm4(uint32_t a, uint32_t r[4]) {
    asm volatile("ldmatrix.sync.aligned.m8n8.x4.shared.b16 {%0,%1,%2,%3},[%4];"
                 : "=r"(r[0]), "=r"(r[1]), "=r"(r[2]), "=r"(r[3]) : "r"(a));
}
__device__ __forceinline__ void ldsm2(uint32_t a, uint32_t r[2]) {
    asm volatile("ldmatrix.sync.aligned.m8n8.x2.shared.b16 {%0,%1},[%2];"
                 : "=r"(r[0]), "=r"(r[1]) : "r"(a));
}

__device__ __forceinline__ void mma_bf(float* c, const uint32_t* a, uint32_t b0, uint32_t b1) {
    asm volatile(
        "mma.sync.aligned.m16n8k16.row.col.f32.bf16.bf16.f32 "
        "{%0,%1,%2,%3},{%4,%5,%6,%7},{%8,%9},{%0,%1,%2,%3};"
        : "+f"(c[0]), "+f"(c[1]), "+f"(c[2]), "+f"(c[3])
        : "r"(a[0]), "r"(a[1]), "r"(a[2]), "r"(a[3]), "r"(b0), "r"(b1));
}

template <int KSTEPS, int NT, int BKS>
__device__ __forceinline__ void gemm1m(uint32_t aA, uint32_t bA, uint32_t bAo,
                                       float c[][4]) {
#pragma unroll
    for (int ks = 0; ks < KSTEPS; ks++) {
        uint32_t a[4];
        ldsm4(aA, a);
#pragma unroll
        for (int p = 0; p < NT / 2; p++) {
            uint32_t b[4];
            ldsm4(bA + p * (16 * BKS * 2), b);
            mma_bf(c[2 * p],     a, b[0], b[1]);
            mma_bf(c[2 * p + 1], a, b[2], b[3]);
        }
        if constexpr (NT & 1) {
            uint32_t b[2];
            ldsm2(bAo, b);
            mma_bf(c[NT - 1], a, b[0], b[1]);
        }
        aA += 32; bA += 32; bAo += 32;
    }
}

template <int KSTEPS, int NT, int BKS>
__device__ __forceinline__ void gemm_dual(uint32_t aA,
                                          uint32_t bA1, uint32_t bAo1,
                                          uint32_t bA2, uint32_t bAo2,
                                          float c1[][4], float c2[][4]) {
#pragma unroll
    for (int ks = 0; ks < KSTEPS; ks++) {
        uint32_t a[4];
        ldsm4(aA, a);
#pragma unroll
        for (int p = 0; p < NT / 2; p++) {
            uint32_t b[4];
            ldsm4(bA1 + p * (16 * BKS * 2), b);
            mma_bf(c1[2 * p],     a, b[0], b[1]);
            mma_bf(c1[2 * p + 1], a, b[2], b[3]);
        }
        if constexpr (NT & 1) {
            uint32_t b[2];
            ldsm2(bAo1, b);
            mma_bf(c1[NT - 1], a, b[0], b[1]);
        }
#pragma unroll
        for (int p = 0; p < NT / 2; p++) {
            uint32_t b[4];
            ldsm4(bA2 + p * (16 * BKS * 2), b);
            mma_bf(c2[2 * p],     a, b[0], b[1]);
            mma_bf(c2[2 * p + 1], a, b[2], b[3]);
        }
        if constexpr (NT & 1) {
            uint32_t b[2];
            ldsm2(bAo2, b);
            mma_bf(c2[NT - 1], a, b[0], b[1]);
        }
        aA += 32; bA1 += 32; bAo1 += 32; bA2 += 32; bAo2 += 32;
    }
}

template <int NT>
__device__ __forceinline__ void store_h(const float c[][4], const float* __restrict__ bias,
                                        uint32_t* __restrict__ hb, int nb, int mrow, int g, int t) {
#pragma unroll
    for (int nt = 0; nt < NT; nt++) {
        int cc = nb + nt * 8 + 2 * t;
        float2 b = *(const float2*)&bias[cc];
#pragma unroll
        for (int h = 0; h < 2; h++) {
            int row = mrow + h * 8 + g;
            float v0 = fmaxf(c[nt][2 * h + 0] + b.x, 0.f);
            float v1 = fmaxf(c[nt][2 * h + 1] + b.y, 0.f);
            __nv_bfloat162 p = __floats2bfloat162_rn(v0, v1);
            hb[row * 60 + (cc >> 1)] = *(uint32_t*)&p;
        }
    }
}

__device__ __forceinline__ void loadW1(const float* __restrict__ Wg, float v[W1N], int tid) {
#pragma unroll
    for (int j = 0; j < W1N; j++) {
        int idx = tid + j * NTH;
        v[j] = (idx < KD * NH) ? Wg[idx] : 0.f;
    }
}
__device__ __forceinline__ void scatW1(const float v[W1N], __nv_bfloat16* __restrict__ dst, int tid) {
#pragma unroll
    for (int j = 0; j < W1N; j++) {
        int idx = tid + j * NTH;
        if (idx < KD * NH) {
            int kk = idx / NH, n = idx - kk * NH;
            dst[n * W1KS + kk] = __float2bfloat16(v[j]);
        }
    }
}

__global__ void __launch_bounds__(NTH, 1) flow_bf16(
    const float* __restrict__ e,
    const float* __restrict__ sW1, const float* __restrict__ sb1,
    const float* __restrict__ sW2, const float* __restrict__ sb2,
    const float* __restrict__ sW3, const float* __restrict__ sb3,
    const float* __restrict__ tW1, const float* __restrict__ tb1,
    const float* __restrict__ tW2, const float* __restrict__ tb2,
    const float* __restrict__ tW3, const float* __restrict__ tb3,
    float* __restrict__ zout, float* __restrict__ ldout)
{
    extern __shared__ float smf[];
    uint32_t* smu = (uint32_t*)smf;
    __nv_bfloat16* smh = (__nv_bfloat16*)smf;

    const int tid = threadIdx.x;
    const int lane = tid & 31, wid = tid >> 5;
    const int g = lane >> 2, t = lane & 3;
    const int mw = wid & 7, nw = wid >> 3;
    const int mrow = mw * 16;
    const int nb2 = nw * 56;
    const int nb3 = nw * 32;
    const int pairBar = 1 + mw;
    const long rowBase = (long)blockIdx.x * TB;

    const float* eR0 = e    + (rowBase + mrow + g)     * TOT + nb3 + 2 * t;
    const float* eR1 = e    + (rowBase + mrow + 8 + g) * TOT + nb3 + 2 * t;
    float*       zR0 = zout + (rowBase + mrow + g)     * TOT + nb3 + 2 * t;
    float*       zR1 = zout + (rowBase + mrow + 8 + g) * TOT + nb3 + 2 * t;

    // ---- preload ----
    for (int w = tid; w < O_B1S; w += NTH) smu[w] = 0u;
    __syncthreads();
    for (int idx = tid; idx < NH * NH; idx += NTH) {
        int in = idx / NH, out = idx - in * NH;
        smh[O_W2S * 2 + out * WKS + in] = __float2bfloat16(sW2[idx]);
        smh[O_W2T * 2 + out * WKS + in] = __float2bfloat16(tW2[idx]);
    }
    for (int idx = tid; idx < NH * KD; idx += NTH) {
        int in = idx / KD, out = idx - in * KD;
        smh[O_W3S * 2 + out * WKS + in] = __float2bfloat16(sW3[idx]);
        smh[O_W3T * 2 + out * WKS + in] = __float2bfloat16(tW3[idx]);
    }
    for (int idx = tid; idx < NPADK; idx += NTH) {
        smf[O_B1S + idx] = (idx < NH) ? sb1[idx] : 0.f;
        smf[O_B2S + idx] = (idx < NH) ? sb2[idx] : 0.f;
        smf[O_B1T + idx] = (idx < NH) ? tb1[idx] : 0.f;
        smf[O_B2T + idx] = (idx < NH) ? tb2[idx] : 0.f;
    }
    for (int idx = tid; idx < KD; idx += NTH) {
        smf[O_B3S + idx] = sb3[idx];
        smf[O_B3T + idx] = tb3[idx];
    }

    // ---- ldmatrix address precompute ----
    const uint32_t smb = sm_u32(smf);
    const int aRow = lane & 15, aK = (lane >> 4) << 3;
    const uint32_t aHB1 = smb + O_HB1 * 4 + ((mrow + aRow) * WKS + aK) * 2;
    const uint32_t aHB2 = smb + O_HB2 * 4 + ((mrow + aRow) * WKS + aK) * 2;
    const uint32_t aZB  = smb + O_ZB * 4 + ((mrow + aRow) * ZBS + aK) * 2;
    const int bRow  = (lane & 7) + ((lane >> 4) << 3);
    const int bK    = ((lane >> 3) & 1) << 3;
    const int bORow = lane & 7;
    const uint32_t bW2S  = smb + O_W2S * 4 + ((nb2 + bRow) * WKS + bK) * 2;
    const uint32_t bW2So = smb + O_W2S * 4 + ((48 + bORow) * WKS + bK) * 2;
    const uint32_t bW2T  = smb + O_W2T * 4 + ((nb2 + bRow) * WKS + bK) * 2;
    const uint32_t bW2To = smb + O_W2T * 4 + ((48 + bORow) * WKS + bK) * 2;
    const uint32_t bW3S  = smb + O_W3S * 4 + ((nb3 + bRow) * WKS + bK) * 2;
    const uint32_t bW3T  = smb + O_W3T * 4 + ((nb3 + bRow) * WKS + bK) * 2;
    const uint32_t bW1S  = smb + O_W1S0 * 4 + ((nb2 + bRow) * W1KS + bK) * 2;
    const uint32_t bW1So = smb + O_W1S0 * 4 + ((48 + bORow) * W1KS + bK) * 2;
    const uint32_t bW1T  = smb + O_W1T0 * 4 + ((nb2 + bRow) * W1KS + bK) * 2;
    const uint32_t bW1To = smb + O_W1T0 * 4 + ((48 + bORow) * W1KS + bK) * 2;

    float accS[7][4], accT[7][4];
#pragma unroll
    for (int b = 0; b < 7; b++)
#pragma unroll
        for (int q = 0; q < 4; q++) { accS[b][q] = 0.f; accT[b][q] = 0.f; }
    float ldacc[2] = {0.f, 0.f};

    __syncthreads();

    // ===== STEP 0: constant fold (inputs identically zero) =====
    {
        if (tid < NH) {
            smf[C_H1S + tid] = __bfloat162float(__float2bfloat16(fmaxf(smf[O_B1S + tid], 0.f)));
            smf[C_H1T + tid] = __bfloat162float(__float2bfloat16(fmaxf(smf[O_B1T + tid], 0.f)));
        }
        __syncthreads();
        if (tid < NH) {
            float d = 0.f;
#pragma unroll 4
            for (int in = 0; in < NH; in++)
                d = fmaf(__bfloat162float(smh[O_W2S * 2 + tid * WKS + in]), smf[C_H1S + in], d);
            smf[C_H2S + tid] = __bfloat162float(__float2bfloat16(fmaxf(d + smf[O_B2S + tid], 0.f)));
        } else if (tid >= 256 && tid < 256 + NH) {
            int o = tid - 256;
            float d = 0.f;
#pragma unroll 4
            for (int in = 0; in < NH; in++)
                d = fmaf(__bfloat162float(smh[O_W2T * 2 + o * WKS + in]), smf[C_H1T + in], d);
            smf[C_H2T + o] = __bfloat162float(__float2bfloat16(fmaxf(d + smf[O_B2T + o], 0.f)));
        }
        __syncthreads();
        if (tid < KD) {
            float d = 0.f;
#pragma unroll 4
            for (int in = 0; in < NH; in++)
                d = fmaf(__bfloat162float(smh[O_W3S * 2 + tid * WKS + in]), smf[C_H2S + in], d);
            float s = sigm(d + smf[O_B3S + tid]);
            smf[C_S0 + tid] = s;
            smf[C_ES0 + tid] = __expf(s);
        } else if (tid >= 256 && tid < 256 + KD) {
            int o = tid - 256;
            float d = 0.f;
#pragma unroll 4
            for (int in = 0; in < NH; in++)
                d = fmaf(__bfloat162float(smh[O_W3T * 2 + o * WKS + in]), smf[C_H2T + in], d);
            smf[C_T0 + o] = sigm(d + smf[O_B3T + o]);
        }
        __syncthreads();
        {
            float2 eV[8];
#pragma unroll
            for (int nt = 0; nt < 4; nt++) {
                eV[nt * 2 + 0] = __ldcs((const float2*)&eR0[nt * 8]);
                eV[nt * 2 + 1] = __ldcs((const float2*)&eR1[nt * 8]);
            }
            float partial = 0.f;
#pragma unroll
            for (int nt = 0; nt < 4; nt++) {
                int cc = nb3 + nt * 8 + 2 * t;
                float s0a = smf[C_S0 + cc],  s0b = smf[C_S0 + cc + 1];
                float exa = smf[C_ES0 + cc], exb = smf[C_ES0 + cc + 1];
                float t0a = smf[C_T0 + cc],  t0b = smf[C_T0 + cc + 1];
                partial += s0a + s0b;
#pragma unroll
                for (int h = 0; h < 2; h++) {
                    int row = mrow + h * 8 + g;
                    float2 e2 = eV[nt * 2 + h];
                    float z0 = exa * e2.x + t0a;
                    float z1 = exb * e2.y + t0b;
                    float* zp = (h == 0) ? (zR0 + nt * 8) : (zR1 + nt * 8);
                    __stcs((float2*)zp, make_float2(z0, z1));
                    __nv_bfloat162 zb = __floats2bfloat162_rn(z0, z1);
                    smu[O_ZB + row * 36 + (cc >> 1)] = *(uint32_t*)&zb;
                }
            }
            ldacc[0] += partial;
            ldacc[1] += partial;
            float w1v[W1N];
            loadW1(sW1, w1v, tid);
            scatW1(w1v, smh + O_W1S0 * 2, tid);
            loadW1(tW1, w1v, tid);
            scatW1(w1v, smh + O_W1T0 * 2, tid);
        }
        __syncthreads();
    }

    // ===== steps 1..7 =====
    for (int i = 1; i < DIMS; i++) {
        const uint32_t rOff = (uint32_t)(((i + 1) & 1) * W1PARB);
        const uint32_t wHalf = (uint32_t)((i & 1) * W1PARH);

        // ---- A: acc += z_{i-1} @ W1[i-1]; h1s -> HB1 ----
        if (nw == 0)
            gemm_dual<4, 7, W1KS>(aZB, bW1S + rOff, bW1So + rOff,
                                  bW1T + rOff, bW1To + rOff, accS, accT);
        else
            gemm_dual<4, 6, W1KS>(aZB, bW1S + rOff, 0, bW1T + rOff, 0, accS, accT);
        if (nw == 0) store_h<7>(accS, smf + O_B1S, smu + O_HB1, nb2, mrow, g, t);
        else         store_h<6>(accS, smf + O_B1S, smu + O_HB1, nb2, mrow, g, t);
        bar_pair(pairBar);

        // ---- B: GEMM2-s ----
        if (nw == 0) {
            float D[7][4] = {};
            gemm1m<7, 7, WKS>(aHB1, bW2S, bW2So, D);
            store_h<7>(D, smf + O_B2S, smu + O_HB2, nb2, mrow, g, t);
        } else {
            float D[6][4] = {};
            gemm1m<7, 6, WKS>(aHB1, bW2S, 0, D);
            store_h<6>(D, smf + O_B2S, smu + O_HB2, nb2, mrow, g, t);
        }
        bar_pair(pairBar);

        // ---- C: GEMM3-s -> sv (regs) + logdet; h1t -> HB1 ----
        float sv[4][4];
        {
            float Ds[4][4] = {};
            gemm1m<7, 4, WKS>(aHB2, bW3S, 0, Ds);
#pragma unroll
            for (int nt = 0; nt < 4; nt++) {
                int cc = nb3 + nt * 8 + 2 * t;
                float2 b3 = *(const float2*)&smf[O_B3S + cc];
#pragma unroll
                for (int h = 0; h < 2; h++) {
                    float v0 = sigm(Ds[nt][2 * h + 0] + b3.x);
                    float v1 = sigm(Ds[nt][2 * h + 1] + b3.y);
                    sv[nt][2 * h + 0] = v0;
                    sv[nt][2 * h + 1] = v1;
                    ldacc[h] += v0 + v1;
                }
            }
            if (nw == 0) store_h<7>(accT, smf + O_B1T, smu + O_HB1, nb2, mrow, g, t);
            else         store_h<6>(accT, smf + O_B1T, smu + O_HB1, nb2, mrow, g, t);
        }
        bar_pair(pairBar);

        // ---- D: W1s LDGs early; L2-prefetch e lines; GEMM2-t; scatter W1s ----
        {
            float w1v[W1N];
            if (i < DIMS - 1) loadW1(sW1 + (size_t)i * KD * NH, w1v, tid);
            // each thread's 8 phase-E e-loads fall in two 128B lines: prefetch them
            prefetchL2(eR0 + i * KD);
            prefetchL2(eR1 + i * KD);
            if (nw == 0) {
                float D[7][4] = {};
                gemm1m<7, 7, WKS>(aHB1, bW2T, bW2To, D);
                store_h<7>(D, smf + O_B2T, smu + O_HB2, nb2, mrow, g, t);
            } else {
                float D[6][4] = {};
                gemm1m<7, 6, WKS>(aHB1, bW2T, 0, D);
                store_h<6>(D, smf + O_B2T, smu + O_HB2, nb2, mrow, g, t);
            }
            if (i < DIMS - 1) scatW1(w1v, smh + O_W1S0 * 2 + wHalf, tid);
        }
        bar_pair(pairBar);

        // ---- E: load e (streaming); GEMM3-t; epilogue; stage W1t ----
        {
            const int eoff = i * KD;
            float2 eV[8];
#pragma unroll
            for (int nt = 0; nt < 4; nt++) {
                eV[nt * 2 + 0] = __ldcs((const float2*)&eR0[eoff + nt * 8]);
                eV[nt * 2 + 1] = __ldcs((const float2*)&eR1[eoff + nt * 8]);
            }

            float Dt[4][4] = {};
            gemm1m<7, 4, WKS>(aHB2, bW3T, 0, Dt);
#pragma unroll
            for (int nt = 0; nt < 4; nt++) {
                int cc = nb3 + nt * 8 + 2 * t;
                float2 b3 = *(const float2*)&smf[O_B3T + cc];
#pragma unroll
                for (int h = 0; h < 2; h++) {
                    int row = mrow + h * 8 + g;
                    float t0 = sigm(Dt[nt][2 * h + 0] + b3.x);
                    float t1 = sigm(Dt[nt][2 * h + 1] + b3.y);
                    float2 e2 = eV[nt * 2 + h];
                    float z0 = __expf(sv[nt][2 * h + 0]) * e2.x + t0;
                    float z1 = __expf(sv[nt][2 * h + 1]) * e2.y + t1;
                    float* zp = (h == 0) ? (zR0 + eoff + nt * 8) : (zR1 + eoff + nt * 8);
                    __stcs((float2*)zp, make_float2(z0, z1));
                    __nv_bfloat162 zb = __floats2bfloat162_rn(z0, z1);
                    smu[O_ZB + row * 36 + (cc >> 1)] = *(uint32_t*)&zb;
                }
            }
            if (i < DIMS - 1) {
                float w1v[W1N];
                loadW1(tW1 + (size_t)i * KD * NH, w1v, tid);
                scatW1(w1v, smh + O_W1T0 * 2 + wHalf, tid);
            }
        }
        __syncthreads();
    }

    // ---- logdet reduction (scratch aliased over ZB, dead now) ----
#pragma unroll
    for (int h = 0; h < 2; h++) {
        int row = mrow + h * 8 + g;
        smf[O_LDP + row * 8 + nw * 4 + t] = ldacc[h];
    }
    __syncthreads();
    if (tid < TB) {
        float v = 0.f;
#pragma unroll
        for (int q = 0; q < 8; q++) v += smf[O_LDP + tid * 8 + q];
        ldout[rowBase + tid] = v;
    }
}

extern "C" void kernel_launch(void* const* d_in, const int* in_sizes, int n_in,
                              void* d_out, int out_size) {
    const float* e   = (const float*)d_in[0];
    // d_in[1] = C (strictly upper-triangular DAG -> incremental layer-1 acc is exact)
    const float* sW1 = (const float*)d_in[2];
    const float* sb1 = (const float*)d_in[3];
    const float* sW2 = (const float*)d_in[4];
    const float* sb2 = (const float*)d_in[5];
    const float* sW3 = (const float*)d_in[6];
    const float* sb3 = (const float*)d_in[7];
    const float* tW1 = (const float*)d_in[8];
    const float* tb1 = (const float*)d_in[9];
    const float* tW2 = (const float*)d_in[10];
    const float* tb2 = (const float*)d_in[11];
    const float* tW3 = (const float*)d_in[12];
    const float* tb3 = (const float*)d_in[13];

    float* out = (float*)d_out;
    const int B = in_sizes[0] / TOT;
    float* zout  = out;
    float* ldout = out + (size_t)B * TOT;

    cudaFuncSetAttribute(flow_bf16, cudaFuncAttributeMaxDynamicSharedMemorySize,
                         SMW * (int)sizeof(float));

    flow_bf16<<<B / TB, NTH, SMW * sizeof(float)>>>(
        e, sW1, sb1, sW2, sb2, sW3, sb3,
        tW1, tb1, tW2, tb2, tW3, tb3,
        zout, ldout);
}